// round 15
// baseline (speedup 1.0000x reference)
#include <cuda_runtime.h>
#include <cuda_fp16.h>
#include <math.h>
#include <stdint.h>

// ---------------------------------------------------------------------------
// HuBERT transformer encoder — fp16 mma.sync GEMMs (3-stage ring, fp16
// split-K partials), flash attention (occ-3 single wave, fixed-max softmax,
// fp16 ctx output), fused residual/LN kernels.
// B=4 S=1024 H=768 L=12 NH=12 DH=64 FF=3072
// ---------------------------------------------------------------------------

#define Bb 4
#define Ss 1024
#define Hh 768
#define Ll 12
#define NHh 12
#define DHh 64
#define FFf 3072
#define Mm (Bb*Ss)
#define EPSf 1e-5f

// ---------------- scratch ----------------------------------------------------
__device__ float g_h[Mm*Hh];
__device__ __half g_parth[3][Mm*Hh];     // FFN2 split-K partials (fp16)
__device__ __half g_ctx[Mm*Hh];          // attention output (fp16)

__device__ __half g_x1[Mm*Hh];
__device__ __half g_f1[(size_t)Mm*FFf];
__device__ __half g_q1[Mm*Hh];
__device__ __half g_k1[Mm*Hh];
__device__ __half g_v1[Mm*Hh];

__device__ __half g_wqt[Ll*Hh*Hh];
__device__ __half g_wkt[Ll*Hh*Hh];
__device__ __half g_wvt[Ll*Hh*Hh];
__device__ __half g_w1t[Ll*FFf*Hh];
__device__ __half g_w2t[Ll*FFf*Hh];

// ---------------- PTX helpers ------------------------------------------------
__device__ __forceinline__ uint32_t smem_u32(const void* p) {
    uint32_t a;
    asm("{ .reg .u64 t; cvta.to.shared.u64 t, %1; cvt.u32.u64 %0, t; }"
        : "=r"(a) : "l"(p));
    return a;
}
__device__ __forceinline__ void cp16(uint32_t sa, const void* g) {
    asm volatile("cp.async.cg.shared.global [%0], [%1], 16;"
                 :: "r"(sa), "l"(g) : "memory");
}
__device__ __forceinline__ void cp_commit() {
    asm volatile("cp.async.commit_group;" ::: "memory");
}
__device__ __forceinline__ void cp_wait1() {
    asm volatile("cp.async.wait_group 1;" ::: "memory");
}
#define LDMX4(R, addr) \
    asm volatile("ldmatrix.sync.aligned.m8n8.x4.shared.b16 {%0,%1,%2,%3}, [%4];" \
        : "=r"((R)[0]), "=r"((R)[1]), "=r"((R)[2]), "=r"((R)[3]) : "r"(addr))
#define LDMX4T(R, addr) \
    asm volatile("ldmatrix.sync.aligned.m8n8.x4.trans.shared.b16 {%0,%1,%2,%3}, [%4];" \
        : "=r"((R)[0]), "=r"((R)[1]), "=r"((R)[2]), "=r"((R)[3]) : "r"(addr))

__device__ __forceinline__ void mmah(float* c, const uint32_t* a,
                                     uint32_t b0, uint32_t b1) {
    asm volatile(
        "mma.sync.aligned.m16n8k16.row.col.f32.f16.f16.f32 "
        "{%0,%1,%2,%3}, {%4,%5,%6,%7}, {%8,%9}, {%0,%1,%2,%3};"
        : "+f"(c[0]), "+f"(c[1]), "+f"(c[2]), "+f"(c[3])
        : "r"(a[0]), "r"(a[1]), "r"(a[2]), "r"(a[3]), "r"(b0), "r"(b1));
}
__device__ __forceinline__ void mmah16(uint32_t* d, const uint32_t* a,
                                       uint32_t b0, uint32_t b1) {
    asm volatile(
        "mma.sync.aligned.m16n8k16.row.col.f16.f16.f16.f16 "
        "{%0,%1}, {%2,%3,%4,%5}, {%6,%7}, {%0,%1};"
        : "+r"(d[0]), "+r"(d[1])
        : "r"(a[0]), "r"(a[1]), "r"(a[2]), "r"(a[3]), "r"(b0), "r"(b1));
}
__device__ __forceinline__ uint32_t pkh(float f0, float f1) {
    __half2 h = __floats2half2_rn(f0, f1);
    return *reinterpret_cast<uint32_t*>(&h);
}

// ---------------------------------------------------------------------------
// Weight transpose to fp16: W[K,N] fp32 -> T[N,K] fp16 (coalesced 8B stores)
// ---------------------------------------------------------------------------
__global__ void k_wt(const float* __restrict__ W,
                     __half* __restrict__ T, int K, int N) {
    __shared__ float t[32][33];
    const size_t off = (size_t)blockIdx.z * K * N;
    const int n0 = blockIdx.x * 32, k0 = blockIdx.y * 32;
    const int tx = threadIdx.x, ty = threadIdx.y;
#pragma unroll
    for (int r = 0; r < 4; r++)
        t[ty + 8 * r][tx] = W[off + (size_t)(k0 + ty + 8 * r) * N + n0 + tx];
    __syncthreads();
    const int tid = ty * 32 + tx;
    const int row = tid >> 3;
    const int seg = tid & 7;
    __half hb[4];
#pragma unroll
    for (int j = 0; j < 4; j++)
        hb[j] = __float2half_rn(t[seg * 4 + j][row]);
    *reinterpret_cast<uint2*>(&T[off + (size_t)(n0 + row) * K + k0 + seg * 4]) =
        *reinterpret_cast<uint2*>(hb);
}

// ---------------------------------------------------------------------------
// Shared GEMM plumbing — 3-stage cp.async ring
// ---------------------------------------------------------------------------
#define ROWB 144
#define STG  36864
#define MG_SMEM (3*STG)

struct GPtrs {
    const __half* w[3];
    const float* bias[3];
    __half* outh[3];
    int aoff[3];
};

__device__ __forceinline__ void issue_chunk(
    uint32_t s0, const __half* A, const __half* B,
    int m0, int n0, int LDK, int cc, int r, int cpart) {
    size_t ka = (size_t)(m0 + r) * LDK + cc * 64 + cpart * 32;
    size_t kb = (size_t)(n0 + r) * LDK + cc * 64 + cpart * 32;
    uint32_t so = (uint32_t)r * ROWB + cpart * 64;
#pragma unroll
    for (int i = 0; i < 4; i++) {
        cp16(s0 + so + 16 * i,         A + ka + 8 * i);
        cp16(s0 + 18432 + so + 16 * i, B + kb + 8 * i);
    }
}

// ---------------------------------------------------------------------------
// fp32-accum GEMM. EPI: 1 bias+GELU->fp16, 4 raw->fp16 partial (split-K)
// ---------------------------------------------------------------------------
template <int EPI>
__global__ void __launch_bounds__(256, 2) k_mgemm(
    const __half* __restrict__ A0, GPtrs P, int KK, int LDK, int NN) {
    extern __shared__ char smem[];
    const int z = blockIdx.z;
    const __half* __restrict__ A = A0 + P.aoff[z];
    const __half* __restrict__ B = P.w[z];

    const int m0 = blockIdx.y << 7, n0 = blockIdx.x << 7;
    const uint32_t sb = smem_u32(smem);
    const int tid = threadIdx.x;
    const int wid = tid >> 5, lane = tid & 31;
    const int wm = (wid >> 2) * 64;
    const int wn = (wid & 3) * 32;

    const int r = tid >> 1, cpart = tid & 1;
    const int NCH = KK / 64;

    float acc[4][4][4];
#pragma unroll
    for (int i = 0; i < 4; i++)
#pragma unroll
        for (int j = 0; j < 4; j++)
#pragma unroll
            for (int k = 0; k < 4; k++) acc[i][j][k] = 0.f;

    issue_chunk(sb,       A, B, m0, n0, LDK, 0, r, cpart); cp_commit();
    issue_chunk(sb + STG, A, B, m0, n0, LDK, 1, r, cpart); cp_commit();

    const uint32_t aoff = (uint32_t)(lane & 15) * ROWB + (lane >> 4) * 16;
    const uint32_t boff = (uint32_t)(((lane >> 4) << 3) + (lane & 7)) * ROWB +
                          ((lane >> 3) & 1) * 16;

    int rd = 0, wr = 2;
    for (int ch = 0; ch < NCH; ch++) {
        const uint32_t s0 = sb + (uint32_t)rd * STG;
        cp_wait1();
        __syncthreads();
        if (ch + 2 < NCH) {
            issue_chunk(sb + (uint32_t)wr * STG, A, B, m0, n0, LDK,
                        ch + 2, r, cpart);
            cp_commit();
        }

#pragma unroll
        for (int ks = 0; ks < 4; ks++) {
            uint32_t bh[2][4];
#pragma unroll
            for (int np = 0; np < 2; np++) {
                uint32_t ad = s0 + 18432 + (uint32_t)(wn + np * 16) * ROWB +
                              boff + ks * 32;
                LDMX4(bh[np], ad);
            }
#pragma unroll
            for (int mt = 0; mt < 4; mt++) {
                uint32_t ad = s0 + (uint32_t)(wm + mt * 16) * ROWB + aoff + ks * 32;
                uint32_t ah[4];
                LDMX4(ah, ad);
#pragma unroll
                for (int nn = 0; nn < 4; nn++) {
                    uint32_t b0 = bh[nn >> 1][(nn & 1) * 2];
                    uint32_t b1 = bh[nn >> 1][(nn & 1) * 2 + 1];
                    mmah(acc[mt][nn], ah, b0, b1);
                }
            }
        }
        rd = (rd == 2) ? 0 : rd + 1;
        wr = (wr == 2) ? 0 : wr + 1;
    }

#pragma unroll
    for (int mt = 0; mt < 4; mt++) {
#pragma unroll
        for (int nn = 0; nn < 4; nn++) {
            int row = m0 + wm + mt * 16 + (lane >> 2);
            int col = n0 + wn + nn * 8 + (lane & 3) * 2;
            float b0 = (EPI == 4) ? 0.f : P.bias[z][col];
            float b1 = (EPI == 4) ? 0.f : P.bias[z][col + 1];
#pragma unroll
            for (int h2 = 0; h2 < 2; h2++) {
                int rr2 = row + h2 * 8;
                float v0 = acc[mt][nn][h2 * 2]     + b0;
                float v1 = acc[mt][nn][h2 * 2 + 1] + b1;
                if (EPI == 1) {
                    v0 = 0.5f * v0 * (1.0f + erff(v0 * 0.70710678118654752f));
                    v1 = 0.5f * v1 * (1.0f + erff(v1 * 0.70710678118654752f));
                }
                *reinterpret_cast<uint32_t*>(
                    P.outh[z] + (size_t)rr2 * NN + col) = pkh(v0, v1);
            }
        }
    }
}

// ---------------------------------------------------------------------------
// fp16-accum GEMM (QKV): bias -> fp16 out
// ---------------------------------------------------------------------------
__global__ void __launch_bounds__(256, 2) k_mgemm16(
    const __half* __restrict__ A, GPtrs P, int KK, int LDK, int NN) {
    extern __shared__ char smem[];
    const int z = blockIdx.z;
    const __half* __restrict__ B = P.w[z];

    const int m0 = blockIdx.y << 7, n0 = blockIdx.x << 7;
    const uint32_t sb = smem_u32(smem);
    const int tid = threadIdx.x;
    const int wid = tid >> 5, lane = tid & 31;
    const int wm = (wid >> 2) * 64;
    const int wn = (wid & 3) * 32;

    const int r = tid >> 1, cpart = tid & 1;
    const int NCH = KK / 64;

    uint32_t acc[4][4][2];
#pragma unroll
    for (int i = 0; i < 4; i++)
#pragma unroll
        for (int j = 0; j < 4; j++) { acc[i][j][0] = 0u; acc[i][j][1] = 0u; }

    issue_chunk(sb,       A, B, m0, n0, LDK, 0, r, cpart); cp_commit();
    issue_chunk(sb + STG, A, B, m0, n0, LDK, 1, r, cpart); cp_commit();

    const uint32_t aoff = (uint32_t)(lane & 15) * ROWB + (lane >> 4) * 16;
    const uint32_t boff = (uint32_t)(((lane >> 4) << 3) + (lane & 7)) * ROWB +
                          ((lane >> 3) & 1) * 16;

    int rd = 0, wr = 2;
    for (int ch = 0; ch < NCH; ch++) {
        const uint32_t s0 = sb + (uint32_t)rd * STG;
        cp_wait1();
        __syncthreads();
        if (ch + 2 < NCH) {
            issue_chunk(sb + (uint32_t)wr * STG, A, B, m0, n0, LDK,
                        ch + 2, r, cpart);
            cp_commit();
        }

#pragma unroll
        for (int ks = 0; ks < 4; ks++) {
            uint32_t bh[2][4];
#pragma unroll
            for (int np = 0; np < 2; np++) {
                uint32_t ad = s0 + 18432 + (uint32_t)(wn + np * 16) * ROWB +
                              boff + ks * 32;
                LDMX4(bh[np], ad);
            }
#pragma unroll
            for (int mt = 0; mt < 4; mt++) {
                uint32_t ad = s0 + (uint32_t)(wm + mt * 16) * ROWB + aoff + ks * 32;
                uint32_t ah[4];
                LDMX4(ah, ad);
#pragma unroll
                for (int nn = 0; nn < 4; nn++) {
                    uint32_t b0 = bh[nn >> 1][(nn & 1) * 2];
                    uint32_t b1 = bh[nn >> 1][(nn & 1) * 2 + 1];
                    mmah16(acc[mt][nn], ah, b0, b1);
                }
            }
        }
        rd = (rd == 2) ? 0 : rd + 1;
        wr = (wr == 2) ? 0 : wr + 1;
    }

#pragma unroll
    for (int mt = 0; mt < 4; mt++) {
#pragma unroll
        for (int nn = 0; nn < 4; nn++) {
            int row = m0 + wm + mt * 16 + (lane >> 2);
            int col = n0 + wn + nn * 8 + (lane & 3) * 2;
            float b0 = P.bias[z][col], b1 = P.bias[z][col + 1];
#pragma unroll
            for (int h2 = 0; h2 < 2; h2++) {
                int rr2 = row + h2 * 8;
                float2 vv = __half22float2(
                    *reinterpret_cast<const __half2*>(&acc[mt][nn][h2]));
                *reinterpret_cast<uint32_t*>(
                    P.outh[z] + (size_t)rr2 * NN + col) =
                    pkh(vv.x + b0, vv.y + b1);
            }
        }
    }
}

// ---------------------------------------------------------------------------
// h += ctx (fp16); then LN -> fp16 x1.  (post-attention residual + LN2)
// ---------------------------------------------------------------------------
__global__ void k_lnadd(const __half* __restrict__ ctx,
                        float* __restrict__ h,
                        const float* __restrict__ gam,
                        const float* __restrict__ bet,
                        __half* __restrict__ oh) {
    const int row = blockIdx.x;
    const int t = threadIdx.x;
    const size_t base = (size_t)row * Hh;
    float v[3];
    float s = 0.f, sq = 0.f;
#pragma unroll
    for (int j = 0; j < 3; j++) {
        int c = t + j * 256;
        float val = h[base + c] + __half2float(ctx[base + c]);
        h[base + c] = val;
        v[j] = val;
        s += val;
        sq += val * val;
    }
#pragma unroll
    for (int o = 16; o; o >>= 1) {
        s  += __shfl_xor_sync(0xffffffffu, s,  o);
        sq += __shfl_xor_sync(0xffffffffu, sq, o);
    }
    __shared__ float ss[8], sv[8];
    if ((t & 31) == 0) { ss[t >> 5] = s; sv[t >> 5] = sq; }
    __syncthreads();
    __shared__ float bm, br;
    if (t == 0) {
        float ts = 0.f, tq = 0.f;
#pragma unroll
        for (int i = 0; i < 8; i++) { ts += ss[i]; tq += sv[i]; }
        float mean = ts * (1.0f / Hh);
        float var  = tq * (1.0f / Hh) - mean * mean;
        bm = mean;
        br = rsqrtf(var + EPSf);
    }
    __syncthreads();
    const float mean = bm, rstd = br;
#pragma unroll
    for (int j = 0; j < 3; j++) {
        int c = t + j * 256;
        float val = (v[j] - mean) * rstd * gam[c] + bet[c];
        oh[base + c] = __float2half_rn(val);
    }
}

// ---------------------------------------------------------------------------
// split-K reduce (fp16 partials, +bias +residual) fused with NEXT layer's LN.
// ---------------------------------------------------------------------------
__global__ void k_redln(const __half* __restrict__ p0, const __half* __restrict__ p1,
                        const __half* __restrict__ p2, const float* __restrict__ bias,
                        float* __restrict__ h,
                        const float* __restrict__ gam, const float* __restrict__ bet,
                        __half* __restrict__ oh) {
    const int row = blockIdx.x;
    const int t = threadIdx.x;
    const size_t base = (size_t)row * Hh;
    float v[3];
    float s = 0.f, sq = 0.f;
#pragma unroll
    for (int j = 0; j < 3; j++) {
        int c = t + j * 256;
        float val = h[base + c] + __half2float(p0[base + c]) +
                    __half2float(p1[base + c]) + __half2float(p2[base + c]) +
                    bias[c];
        h[base + c] = val;
        v[j] = val;
        s += val;
        sq += val * val;
    }
#pragma unroll
    for (int o = 16; o; o >>= 1) {
        s  += __shfl_xor_sync(0xffffffffu, s,  o);
        sq += __shfl_xor_sync(0xffffffffu, sq, o);
    }
    __shared__ float ss[8], sv[8];
    if ((t & 31) == 0) { ss[t >> 5] = s; sv[t >> 5] = sq; }
    __syncthreads();
    __shared__ float bm, br;
    if (t == 0) {
        float ts = 0.f, tq = 0.f;
#pragma unroll
        for (int i = 0; i < 8; i++) { ts += ss[i]; tq += sv[i]; }
        float mean = ts * (1.0f / Hh);
        float var  = tq * (1.0f / Hh) - mean * mean;
        bm = mean;
        br = rsqrtf(var + EPSf);
    }
    __syncthreads();
    const float mean = bm, rstd = br;
#pragma unroll
    for (int j = 0; j < 3; j++) {
        int c = t + j * 256;
        float val = (v[j] - mean) * rstd * gam[c] + bet[c];
        oh[base + c] = __float2half_rn(val);
    }
}

// last layer: reduce + final LN -> fp32 out
__global__ void k_redlnf(const __half* __restrict__ p0, const __half* __restrict__ p1,
                         const __half* __restrict__ p2, const float* __restrict__ bias,
                         const float* __restrict__ h,
                         const float* __restrict__ gam, const float* __restrict__ bet,
                         float* __restrict__ out) {
    const int row = blockIdx.x;
    const int t = threadIdx.x;
    const size_t base = (size_t)row * Hh;
    float v[3];
    float s = 0.f, sq = 0.f;
#pragma unroll
    for (int j = 0; j < 3; j++) {
        int c = t + j * 256;
        float val = h[base + c] + __half2float(p0[base + c]) +
                    __half2float(p1[base + c]) + __half2float(p2[base + c]) +
                    bias[c];
        v[j] = val;
        s += val;
        sq += val * val;
    }
#pragma unroll
    for (int o = 16; o; o >>= 1) {
        s  += __shfl_xor_sync(0xffffffffu, s,  o);
        sq += __shfl_xor_sync(0xffffffffu, sq, o);
    }
    __shared__ float ss[8], sv[8];
    if ((t & 31) == 0) { ss[t >> 5] = s; sv[t >> 5] = sq; }
    __syncthreads();
    __shared__ float bm, br;
    if (t == 0) {
        float ts = 0.f, tq = 0.f;
#pragma unroll
        for (int i = 0; i < 8; i++) { ts += ss[i]; tq += sv[i]; }
        float mean = ts * (1.0f / Hh);
        float var  = tq * (1.0f / Hh) - mean * mean;
        bm = mean;
        br = rsqrtf(var + EPSf);
    }
    __syncthreads();
    const float mean = bm, rstd = br;
#pragma unroll
    for (int j = 0; j < 3; j++) {
        int c = t + j * 256;
        out[base + c] = (v[j] - mean) * rstd * gam[c] + bet[c];
    }
}

// ---------------------------------------------------------------------------
// Flash attention — occ 3 (single wave of 384 CTAs), fixed-max softmax,
// 3-stage KV ring, 1 sync/tile, fp16 ctx output.
// ---------------------------------------------------------------------------
#define FRB 144
#define SQ0 0
#define SKV0 18432
#define KVSTG 18432
#define SMB (SKV0 + 3*KVSTG)
#define FL_SMEM (SMB + 2048)

__device__ __forceinline__ void flash_issue_kv(
    uint32_t base, const __half* K1, const __half* V1,
    int b, int hh, int kt, int tid) {
    int r = tid >> 2, cpart = tid & 3;
    size_t g = ((size_t)(b * Ss + kt * 64 + r)) * Hh + hh * DHh + cpart * 16;
    uint32_t so = (uint32_t)r * FRB + cpart * 32;
    cp16(base + so,         K1 + g); cp16(base + so + 16,        K1 + g + 8);
    cp16(base + 9216 + so,  V1 + g); cp16(base + 9216 + so + 16, V1 + g + 8);
}

__global__ void __launch_bounds__(256, 3) k_flash(
    const __half* __restrict__ Q1,
    const __half* __restrict__ K1,
    const __half* __restrict__ V1,
    const int* __restrict__ mask, __half* __restrict__ CTX) {
    extern __shared__ char smem[];
    const int bh = blockIdx.y;
    const int b = bh / NHh, hh = bh - b * NHh;
    const int q0 = blockIdx.x * 128;
    const uint32_t sb = smem_u32(smem);
    const int tid = threadIdx.x, wid = tid >> 5, lane = tid & 31;
    const float scale = 0.125f;

    {
        int r = tid >> 1, cpart = tid & 1;
        size_t g = ((size_t)(b * Ss + q0 + r)) * Hh + hh * DHh + cpart * 32;
        uint32_t so = (uint32_t)r * FRB + cpart * 64;
#pragma unroll
        for (int i = 0; i < 4; i++)
            cp16(sb + SQ0 + so + 16 * i, Q1 + g + 8 * i);
    }
    flash_issue_kv(sb + SKV0, K1, V1, b, hh, 0, tid);
    cp_commit();
    flash_issue_kv(sb + SKV0 + KVSTG, K1, V1, b, hh, 1, tid);
    cp_commit();

#pragma unroll
    for (int i = 0; i < 4; i++) {
        int kx = tid + i * 256;
        float mb = (mask[b * Ss + kx] == 0) ? -10000.0f : 0.0f;
        *reinterpret_cast<__half*>(smem + SMB + kx * 2) = __float2half_rn(mb);
    }

    float O[8][4];
#pragma unroll
    for (int i = 0; i < 8; i++)
#pragma unroll
        for (int j = 0; j < 4; j++) O[i][j] = 0.f;
    float l0 = 0.f, l1 = 0.f;

    const uint32_t aoff = (uint32_t)(16 * wid + (lane & 15)) * FRB +
                          ((lane >> 4) & 1) * 16;
    const uint32_t koff = (uint32_t)(((lane >> 4) << 3) + (lane & 7)) * FRB +
                          ((lane >> 3) & 1) * 16;
    const uint32_t voff = (uint32_t)(lane & 15) * FRB + ((lane >> 4) & 1) * 16;

    for (int kt = 0; kt < 16; kt++) {
        const uint32_t kv = sb + SKV0 + (uint32_t)(kt % 3) * KVSTG;
        cp_wait1();
        __syncthreads();
        if (kt + 2 < 16) {
            flash_issue_kv(sb + SKV0 + (uint32_t)((kt + 2) % 3) * KVSTG,
                           K1, V1, b, hh, kt + 2, tid);
            cp_commit();
        }

        uint32_t sh16[8][2];
#pragma unroll
        for (int i = 0; i < 8; i++) { sh16[i][0] = 0u; sh16[i][1] = 0u; }

#pragma unroll
        for (int s = 0; s < 4; s++) {
            uint32_t qa = sb + SQ0 + aoff + s * 32;
            uint32_t ah[4];
            LDMX4(ah, qa);
#pragma unroll
            for (int jp = 0; jp < 4; jp++) {
                uint32_t ka = kv + (uint32_t)(16 * jp) * FRB + koff + s * 32;
                uint32_t kh4[4];
                LDMX4(kh4, ka);
#pragma unroll
                for (int half = 0; half < 2; half++)
                    mmah16(sh16[2 * jp + half], ah,
                           kh4[half * 2], kh4[half * 2 + 1]);
            }
        }

        float sacc[8][4];
#pragma unroll
        for (int j = 0; j < 8; j++) {
            float2 s01 = __half22float2(
                *reinterpret_cast<const __half2*>(&sh16[j][0]));
            float2 s23 = __half22float2(
                *reinterpret_cast<const __half2*>(&sh16[j][1]));
            float2 mbv = __half22float2(*reinterpret_cast<const __half2*>(
                smem + SMB + (kt * 64 + 8 * j + 2 * (lane & 3)) * 2));
            float p0 = __expf(s01.x * scale + mbv.x);
            float p1 = __expf(s01.y * scale + mbv.y);
            float p2 = __expf(s23.x * scale + mbv.x);
            float p3 = __expf(s23.y * scale + mbv.y);
            sacc[j][0] = p0; sacc[j][1] = p1; sacc[j][2] = p2; sacc[j][3] = p3;
            l0 += p0 + p1; l1 += p2 + p3;
        }

#pragma unroll
        for (int s = 0; s < 4; s++) {
            uint32_t ph[4];
            ph[0] = pkh(sacc[2 * s][0],     sacc[2 * s][1]);
            ph[1] = pkh(sacc[2 * s][2],     sacc[2 * s][3]);
            ph[2] = pkh(sacc[2 * s + 1][0], sacc[2 * s + 1][1]);
            ph[3] = pkh(sacc[2 * s + 1][2], sacc[2 * s + 1][3]);
#pragma unroll
            for (int dp = 0; dp < 4; dp++) {
                uint32_t va = kv + 9216 + (uint32_t)(16 * s) * FRB + voff + dp * 32;
                uint32_t vh4[4];
                LDMX4T(vh4, va);
#pragma unroll
                for (int half = 0; half < 2; half++)
                    mmah(O[2 * dp + half], ph,
                         vh4[half * 2], vh4[half * 2 + 1]);
            }
        }
    }

    l0 += __shfl_xor_sync(0xffffffffu, l0, 1);
    l0 += __shfl_xor_sync(0xffffffffu, l0, 2);
    l1 += __shfl_xor_sync(0xffffffffu, l1, 1);
    l1 += __shfl_xor_sync(0xffffffffu, l1, 2);
    float i0 = 1.0f / l0, i1 = 1.0f / l1;
    int r0 = b * Ss + q0 + 16 * wid + (lane >> 2);
#pragma unroll
    for (int jd = 0; jd < 8; jd++) {
        int col = hh * DHh + 8 * jd + 2 * (lane & 3);
        *reinterpret_cast<uint32_t*>(&CTX[(size_t)r0 * Hh + col]) =
            pkh(O[jd][0] * i0, O[jd][1] * i0);
        *reinterpret_cast<uint32_t*>(&CTX[(size_t)(r0 + 8) * Hh + col]) =
            pkh(O[jd][2] * i1, O[jd][3] * i1);
    }
}

// ---------------------------------------------------------------------------
// h = hidden + pos_emb
// ---------------------------------------------------------------------------
__global__ void k_addpos(const float* __restrict__ hid,
                         const float* __restrict__ pos,
                         float* __restrict__ out) {
    int i = blockIdx.x * 256 + threadIdx.x;
    const int PER_B = Ss * Hh / 4;
    float4 a = reinterpret_cast<const float4*>(hid)[i];
    float4 p = reinterpret_cast<const float4*>(pos)[i % PER_B];
    a.x += p.x; a.y += p.y; a.z += p.z; a.w += p.w;
    reinterpret_cast<float4*>(out)[i] = a;
}

// ---------------------------------------------------------------------------
// LayerNorm -> fp16 (layer-0 LN1 only)
// ---------------------------------------------------------------------------
__global__ void k_ln_h(const float* __restrict__ in,
                       const float* __restrict__ gam,
                       const float* __restrict__ bet,
                       __half* __restrict__ oh) {
    const int row = blockIdx.x;
    const int t = threadIdx.x;
    const float* x = in + (size_t)row * Hh;
    float v[3];
    float s = 0.f, sq = 0.f;
#pragma unroll
    for (int j = 0; j < 3; j++) {
        v[j] = x[t + j * 256];
        s += v[j];
        sq += v[j] * v[j];
    }
#pragma unroll
    for (int o = 16; o; o >>= 1) {
        s  += __shfl_xor_sync(0xffffffffu, s,  o);
        sq += __shfl_xor_sync(0xffffffffu, sq, o);
    }
    __shared__ float ss[8], sv[8];
    if ((t & 31) == 0) { ss[t >> 5] = s; sv[t >> 5] = sq; }
    __syncthreads();
    __shared__ float bm, br;
    if (t == 0) {
        float ts = 0.f, tq = 0.f;
#pragma unroll
        for (int i = 0; i < 8; i++) { ts += ss[i]; tq += sv[i]; }
        float mean = ts * (1.0f / Hh);
        float var  = tq * (1.0f / Hh) - mean * mean;
        bm = mean;
        br = rsqrtf(var + EPSf);
    }
    __syncthreads();
    const float mean = bm, rstd = br;
#pragma unroll
    for (int j = 0; j < 3; j++) {
        int c = t + j * 256;
        float val = (v[j] - mean) * rstd * gam[c] + bet[c];
        oh[(size_t)row * Hh + c] = __float2half_rn(val);
    }
}

// ---------------------------------------------------------------------------
// Launch
// ---------------------------------------------------------------------------
extern "C" void kernel_launch(void* const* d_in, const int* in_sizes, int n_in,
                              void* d_out, int out_size) {
    const float* hid  = (const float*)d_in[0];
    const int*   mask = (const int*)  d_in[1];
    const float* pos  = (const float*)d_in[2];
    const float* Wq   = (const float*)d_in[3];
    const float* bq   = (const float*)d_in[4];
    const float* Wk   = (const float*)d_in[5];
    const float* bk   = (const float*)d_in[6];
    const float* Wv   = (const float*)d_in[7];
    const float* bv   = (const float*)d_in[8];
    const float* l1s  = (const float*)d_in[9];
    const float* l1b  = (const float*)d_in[10];
    const float* l2s  = (const float*)d_in[11];
    const float* l2b  = (const float*)d_in[12];
    const float* W1   = (const float*)d_in[13];
    const float* b1   = (const float*)d_in[14];
    const float* W2   = (const float*)d_in[15];
    const float* b2   = (const float*)d_in[16];
    const float* lnfs = (const float*)d_in[17];
    const float* lnfb = (const float*)d_in[18];
    float* out = (float*)d_out;

    float* h;
    __half *parth, *ctx;
    cudaGetSymbolAddress((void**)&h, g_h);
    cudaGetSymbolAddress((void**)&parth, g_parth);
    cudaGetSymbolAddress((void**)&ctx, g_ctx);

    __half *x1, *f1, *q1, *k1, *v1;
    cudaGetSymbolAddress((void**)&x1, g_x1);
    cudaGetSymbolAddress((void**)&f1, g_f1);
    cudaGetSymbolAddress((void**)&q1, g_q1);
    cudaGetSymbolAddress((void**)&k1, g_k1);
    cudaGetSymbolAddress((void**)&v1, g_v1);

    __half *wq, *wk, *wv, *w1, *w2;
    cudaGetSymbolAddress((void**)&wq, g_wqt);
    cudaGetSymbolAddress((void**)&wk, g_wkt);
    cudaGetSymbolAddress((void**)&wv, g_wvt);
    cudaGetSymbolAddress((void**)&w1, g_w1t);
    cudaGetSymbolAddress((void**)&w2, g_w2t);

    cudaFuncSetAttribute(k_mgemm<1>, cudaFuncAttributeMaxDynamicSharedMemorySize, MG_SMEM);
    cudaFuncSetAttribute(k_mgemm<4>, cudaFuncAttributeMaxDynamicSharedMemorySize, MG_SMEM);
    cudaFuncSetAttribute(k_mgemm16, cudaFuncAttributeMaxDynamicSharedMemorySize, MG_SMEM);
    cudaFuncSetAttribute(k_flash,    cudaFuncAttributeMaxDynamicSharedMemorySize, FL_SMEM);

    // weight transpose to fp16
    {
        dim3 blk(32, 8);
        k_wt<<<dim3(Hh / 32, Hh / 32, Ll), blk>>>(Wq, wq, Hh, Hh);
        k_wt<<<dim3(Hh / 32, Hh / 32, Ll), blk>>>(Wk, wk, Hh, Hh);
        k_wt<<<dim3(Hh / 32, Hh / 32, Ll), blk>>>(Wv, wv, Hh, Hh);
        k_wt<<<dim3(FFf / 32, Hh / 32, Ll), blk>>>(W1, w1, Hh, FFf);
        k_wt<<<dim3(Hh / 32, FFf / 32, Ll), blk>>>(W2, w2, FFf, Hh);
    }

    k_addpos<<<(Mm * Hh / 4) / 256, 256>>>(hid, pos, h);
    k_ln_h<<<Mm, 256>>>(h, l1s, l1b, x1);

    for (int l = 0; l < Ll; l++) {
        const size_t wOff = (size_t)l * Hh * Hh;
        const size_t fOff = (size_t)l * Hh * FFf;

        // fused QKV (fp16 accum) -> fp16
        {
            GPtrs P = {};
            P.w[0] = wq + wOff; P.w[1] = wk + wOff; P.w[2] = wv + wOff;
            P.bias[0] = bq + l * Hh; P.bias[1] = bk + l * Hh; P.bias[2] = bv + l * Hh;
            P.outh[0] = q1; P.outh[1] = k1; P.outh[2] = v1;
            k_mgemm16<<<dim3(Hh / 128, Mm / 128, 3), 256, MG_SMEM>>>(
                x1, P, Hh, Hh, Hh);
        }

        // flash -> fp16 ctx (single wave at occ 3)
        k_flash<<<dim3(Ss / 128, Bb * NHh), 256, FL_SMEM>>>(
            q1, k1, v1, mask, ctx);

        // h += ctx; LN2 -> x1
        k_lnadd<<<Mm, 256>>>(ctx, h, l2s + l * Hh, l2b + l * Hh, x1);

        // FFN1: GELU(x @ W1 + b1) -> fp16
        {
            GPtrs P = {};
            P.w[0] = w1 + fOff;
            P.bias[0] = b1 + l * FFf;
            P.outh[0] = f1;
            k_mgemm<1><<<dim3(FFf / 128, Mm / 128, 1), 256, MG_SMEM>>>(
                x1, P, Hh, Hh, FFf);
        }
        // FFN2 split-K x3 partials (fp16)
        {
            GPtrs P = {};
            P.w[0] = w2 + fOff;        P.w[1] = w2 + fOff + 1024;
            P.w[2] = w2 + fOff + 2048;
            P.aoff[0] = 0; P.aoff[1] = 1024; P.aoff[2] = 2048;
            P.outh[0] = parth;
            P.outh[1] = parth + (size_t)Mm * Hh;
            P.outh[2] = parth + 2 * (size_t)Mm * Hh;
            k_mgemm<4><<<dim3(Hh / 128, Mm / 128, 3), 256, MG_SMEM>>>(
                f1, P, 1024, FFf, Hh);
        }
        // reduce + residual, fused with next LN1 (or final LN on last layer)
        if (l + 1 < Ll) {
            k_redln<<<Mm, 256>>>(
                parth, parth + (size_t)Mm * Hh, parth + 2 * (size_t)Mm * Hh,
                b2 + l * Hh, h, l1s + (l + 1) * Hh, l1b + (l + 1) * Hh, x1);
        } else {
            k_redlnf<<<Mm, 256>>>(
                parth, parth + (size_t)Mm * Hh, parth + 2 * (size_t)Mm * Hh,
                b2 + l * Hh, h, lnfs, lnfb, out);
        }
    }
}

// round 16
// speedup vs baseline: 1.0055x; 1.0055x over previous
#include <cuda_runtime.h>
#include <cuda_fp16.h>
#include <math.h>
#include <stdint.h>

// ---------------------------------------------------------------------------
// HuBERT transformer encoder — fp16 mma.sync GEMMs (3-stage ring, fp16
// split-K partials), flash attention (occ-2, Q-in-regs, fixed-max softmax,
// fp16 ctx output), fully fused residual/LN kernels.
// B=4 S=1024 H=768 L=12 NH=12 DH=64 FF=3072
// ---------------------------------------------------------------------------

#define Bb 4
#define Ss 1024
#define Hh 768
#define Ll 12
#define NHh 12
#define DHh 64
#define FFf 3072
#define Mm (Bb*Ss)
#define EPSf 1e-5f

// ---------------- scratch ----------------------------------------------------
__device__ float g_h[Mm*Hh];
__device__ __half g_parth[3][Mm*Hh];     // FFN2 split-K partials (fp16)
__device__ __half g_ctx[Mm*Hh];          // attention output (fp16)

__device__ __half g_x1[Mm*Hh];
__device__ __half g_f1[(size_t)Mm*FFf];
__device__ __half g_q1[Mm*Hh];
__device__ __half g_k1[Mm*Hh];
__device__ __half g_v1[Mm*Hh];

__device__ __half g_wqt[Ll*Hh*Hh];
__device__ __half g_wkt[Ll*Hh*Hh];
__device__ __half g_wvt[Ll*Hh*Hh];
__device__ __half g_w1t[Ll*FFf*Hh];
__device__ __half g_w2t[Ll*FFf*Hh];

// ---------------- PTX helpers ------------------------------------------------
__device__ __forceinline__ uint32_t smem_u32(const void* p) {
    uint32_t a;
    asm("{ .reg .u64 t; cvta.to.shared.u64 t, %1; cvt.u32.u64 %0, t; }"
        : "=r"(a) : "l"(p));
    return a;
}
__device__ __forceinline__ void cp16(uint32_t sa, const void* g) {
    asm volatile("cp.async.cg.shared.global [%0], [%1], 16;"
                 :: "r"(sa), "l"(g) : "memory");
}
__device__ __forceinline__ void cp_commit() {
    asm volatile("cp.async.commit_group;" ::: "memory");
}
__device__ __forceinline__ void cp_wait1() {
    asm volatile("cp.async.wait_group 1;" ::: "memory");
}
#define LDMX4(R, addr) \
    asm volatile("ldmatrix.sync.aligned.m8n8.x4.shared.b16 {%0,%1,%2,%3}, [%4];" \
        : "=r"((R)[0]), "=r"((R)[1]), "=r"((R)[2]), "=r"((R)[3]) : "r"(addr))
#define LDMX4T(R, addr) \
    asm volatile("ldmatrix.sync.aligned.m8n8.x4.trans.shared.b16 {%0,%1,%2,%3}, [%4];" \
        : "=r"((R)[0]), "=r"((R)[1]), "=r"((R)[2]), "=r"((R)[3]) : "r"(addr))

__device__ __forceinline__ void mmah(float* c, const uint32_t* a,
                                     uint32_t b0, uint32_t b1) {
    asm volatile(
        "mma.sync.aligned.m16n8k16.row.col.f32.f16.f16.f32 "
        "{%0,%1,%2,%3}, {%4,%5,%6,%7}, {%8,%9}, {%0,%1,%2,%3};"
        : "+f"(c[0]), "+f"(c[1]), "+f"(c[2]), "+f"(c[3])
        : "r"(a[0]), "r"(a[1]), "r"(a[2]), "r"(a[3]), "r"(b0), "r"(b1));
}
__device__ __forceinline__ void mmah16(uint32_t* d, const uint32_t* a,
                                       uint32_t b0, uint32_t b1) {
    asm volatile(
        "mma.sync.aligned.m16n8k16.row.col.f16.f16.f16.f16 "
        "{%0,%1}, {%2,%3,%4,%5}, {%6,%7}, {%0,%1};"
        : "+r"(d[0]), "+r"(d[1])
        : "r"(a[0]), "r"(a[1]), "r"(a[2]), "r"(a[3]), "r"(b0), "r"(b1));
}
__device__ __forceinline__ uint32_t pkh(float f0, float f1) {
    __half2 h = __floats2half2_rn(f0, f1);
    return *reinterpret_cast<uint32_t*>(&h);
}

// ---------------------------------------------------------------------------
// Weight transpose to fp16: W[K,N] fp32 -> T[N,K] fp16 (coalesced 8B stores)
// ---------------------------------------------------------------------------
__global__ void k_wt(const float* __restrict__ W,
                     __half* __restrict__ T, int K, int N) {
    __shared__ float t[32][33];
    const size_t off = (size_t)blockIdx.z * K * N;
    const int n0 = blockIdx.x * 32, k0 = blockIdx.y * 32;
    const int tx = threadIdx.x, ty = threadIdx.y;
#pragma unroll
    for (int r = 0; r < 4; r++)
        t[ty + 8 * r][tx] = W[off + (size_t)(k0 + ty + 8 * r) * N + n0 + tx];
    __syncthreads();
    const int tid = ty * 32 + tx;
    const int row = tid >> 3;
    const int seg = tid & 7;
    __half hb[4];
#pragma unroll
    for (int j = 0; j < 4; j++)
        hb[j] = __float2half_rn(t[seg * 4 + j][row]);
    *reinterpret_cast<uint2*>(&T[off + (size_t)(n0 + row) * K + k0 + seg * 4]) =
        *reinterpret_cast<uint2*>(hb);
}

// ---------------------------------------------------------------------------
// Shared GEMM plumbing — 3-stage cp.async ring
// ---------------------------------------------------------------------------
#define ROWB 144
#define STG  36864
#define MG_SMEM (3*STG)

struct GPtrs {
    const __half* w[3];
    const float* bias[3];
    __half* outh[3];
    int aoff[3];
};

__device__ __forceinline__ void issue_chunk(
    uint32_t s0, const __half* A, const __half* B,
    int m0, int n0, int LDK, int cc, int r, int cpart) {
    size_t ka = (size_t)(m0 + r) * LDK + cc * 64 + cpart * 32;
    size_t kb = (size_t)(n0 + r) * LDK + cc * 64 + cpart * 32;
    uint32_t so = (uint32_t)r * ROWB + cpart * 64;
#pragma unroll
    for (int i = 0; i < 4; i++) {
        cp16(s0 + so + 16 * i,         A + ka + 8 * i);
        cp16(s0 + 18432 + so + 16 * i, B + kb + 8 * i);
    }
}

// ---------------------------------------------------------------------------
// fp32-accum GEMM. EPI: 1 bias+GELU->fp16, 4 raw->fp16 partial (split-K)
// ---------------------------------------------------------------------------
template <int EPI>
__global__ void __launch_bounds__(256, 2) k_mgemm(
    const __half* __restrict__ A0, GPtrs P, int KK, int LDK, int NN) {
    extern __shared__ char smem[];
    const int z = blockIdx.z;
    const __half* __restrict__ A = A0 + P.aoff[z];
    const __half* __restrict__ B = P.w[z];

    const int m0 = blockIdx.y << 7, n0 = blockIdx.x << 7;
    const uint32_t sb = smem_u32(smem);
    const int tid = threadIdx.x;
    const int wid = tid >> 5, lane = tid & 31;
    const int wm = (wid >> 2) * 64;
    const int wn = (wid & 3) * 32;

    const int r = tid >> 1, cpart = tid & 1;
    const int NCH = KK / 64;

    float acc[4][4][4];
#pragma unroll
    for (int i = 0; i < 4; i++)
#pragma unroll
        for (int j = 0; j < 4; j++)
#pragma unroll
            for (int k = 0; k < 4; k++) acc[i][j][k] = 0.f;

    issue_chunk(sb,       A, B, m0, n0, LDK, 0, r, cpart); cp_commit();
    issue_chunk(sb + STG, A, B, m0, n0, LDK, 1, r, cpart); cp_commit();

    const uint32_t aoff = (uint32_t)(lane & 15) * ROWB + (lane >> 4) * 16;
    const uint32_t boff = (uint32_t)(((lane >> 4) << 3) + (lane & 7)) * ROWB +
                          ((lane >> 3) & 1) * 16;

    int rd = 0, wr = 2;
    for (int ch = 0; ch < NCH; ch++) {
        const uint32_t s0 = sb + (uint32_t)rd * STG;
        cp_wait1();
        __syncthreads();
        if (ch + 2 < NCH) {
            issue_chunk(sb + (uint32_t)wr * STG, A, B, m0, n0, LDK,
                        ch + 2, r, cpart);
            cp_commit();
        }

#pragma unroll
        for (int ks = 0; ks < 4; ks++) {
            uint32_t bh[2][4];
#pragma unroll
            for (int np = 0; np < 2; np++) {
                uint32_t ad = s0 + 18432 + (uint32_t)(wn + np * 16) * ROWB +
                              boff + ks * 32;
                LDMX4(bh[np], ad);
            }
#pragma unroll
            for (int mt = 0; mt < 4; mt++) {
                uint32_t ad = s0 + (uint32_t)(wm + mt * 16) * ROWB + aoff + ks * 32;
                uint32_t ah[4];
                LDMX4(ah, ad);
#pragma unroll
                for (int nn = 0; nn < 4; nn++) {
                    uint32_t b0 = bh[nn >> 1][(nn & 1) * 2];
                    uint32_t b1 = bh[nn >> 1][(nn & 1) * 2 + 1];
                    mmah(acc[mt][nn], ah, b0, b1);
                }
            }
        }
        rd = (rd == 2) ? 0 : rd + 1;
        wr = (wr == 2) ? 0 : wr + 1;
    }

#pragma unroll
    for (int mt = 0; mt < 4; mt++) {
#pragma unroll
        for (int nn = 0; nn < 4; nn++) {
            int row = m0 + wm + mt * 16 + (lane >> 2);
            int col = n0 + wn + nn * 8 + (lane & 3) * 2;
            float b0 = (EPI == 4) ? 0.f : P.bias[z][col];
            float b1 = (EPI == 4) ? 0.f : P.bias[z][col + 1];
#pragma unroll
            for (int h2 = 0; h2 < 2; h2++) {
                int rr2 = row + h2 * 8;
                float v0 = acc[mt][nn][h2 * 2]     + b0;
                float v1 = acc[mt][nn][h2 * 2 + 1] + b1;
                if (EPI == 1) {
                    v0 = 0.5f * v0 * (1.0f + erff(v0 * 0.70710678118654752f));
                    v1 = 0.5f * v1 * (1.0f + erff(v1 * 0.70710678118654752f));
                }
                *reinterpret_cast<uint32_t*>(
                    P.outh[z] + (size_t)rr2 * NN + col) = pkh(v0, v1);
            }
        }
    }
}

// ---------------------------------------------------------------------------
// fp16-accum GEMM (QKV): bias -> fp16 out
// ---------------------------------------------------------------------------
__global__ void __launch_bounds__(256, 2) k_mgemm16(
    const __half* __restrict__ A, GPtrs P, int KK, int LDK, int NN) {
    extern __shared__ char smem[];
    const int z = blockIdx.z;
    const __half* __restrict__ B = P.w[z];

    const int m0 = blockIdx.y << 7, n0 = blockIdx.x << 7;
    const uint32_t sb = smem_u32(smem);
    const int tid = threadIdx.x;
    const int wid = tid >> 5, lane = tid & 31;
    const int wm = (wid >> 2) * 64;
    const int wn = (wid & 3) * 32;

    const int r = tid >> 1, cpart = tid & 1;
    const int NCH = KK / 64;

    uint32_t acc[4][4][2];
#pragma unroll
    for (int i = 0; i < 4; i++)
#pragma unroll
        for (int j = 0; j < 4; j++) { acc[i][j][0] = 0u; acc[i][j][1] = 0u; }

    issue_chunk(sb,       A, B, m0, n0, LDK, 0, r, cpart); cp_commit();
    issue_chunk(sb + STG, A, B, m0, n0, LDK, 1, r, cpart); cp_commit();

    const uint32_t aoff = (uint32_t)(lane & 15) * ROWB + (lane >> 4) * 16;
    const uint32_t boff = (uint32_t)(((lane >> 4) << 3) + (lane & 7)) * ROWB +
                          ((lane >> 3) & 1) * 16;

    int rd = 0, wr = 2;
    for (int ch = 0; ch < NCH; ch++) {
        const uint32_t s0 = sb + (uint32_t)rd * STG;
        cp_wait1();
        __syncthreads();
        if (ch + 2 < NCH) {
            issue_chunk(sb + (uint32_t)wr * STG, A, B, m0, n0, LDK,
                        ch + 2, r, cpart);
            cp_commit();
        }

#pragma unroll
        for (int ks = 0; ks < 4; ks++) {
            uint32_t bh[2][4];
#pragma unroll
            for (int np = 0; np < 2; np++) {
                uint32_t ad = s0 + 18432 + (uint32_t)(wn + np * 16) * ROWB +
                              boff + ks * 32;
                LDMX4(bh[np], ad);
            }
#pragma unroll
            for (int mt = 0; mt < 4; mt++) {
                uint32_t ad = s0 + (uint32_t)(wm + mt * 16) * ROWB + aoff + ks * 32;
                uint32_t ah[4];
                LDMX4(ah, ad);
#pragma unroll
                for (int nn = 0; nn < 4; nn++) {
                    uint32_t b0 = bh[nn >> 1][(nn & 1) * 2];
                    uint32_t b1 = bh[nn >> 1][(nn & 1) * 2 + 1];
                    mmah16(acc[mt][nn], ah, b0, b1);
                }
            }
        }
        rd = (rd == 2) ? 0 : rd + 1;
        wr = (wr == 2) ? 0 : wr + 1;
    }

#pragma unroll
    for (int mt = 0; mt < 4; mt++) {
#pragma unroll
        for (int nn = 0; nn < 4; nn++) {
            int row = m0 + wm + mt * 16 + (lane >> 2);
            int col = n0 + wn + nn * 8 + (lane & 3) * 2;
            float b0 = P.bias[z][col], b1 = P.bias[z][col + 1];
#pragma unroll
            for (int h2 = 0; h2 < 2; h2++) {
                int rr2 = row + h2 * 8;
                float2 vv = __half22float2(
                    *reinterpret_cast<const __half2*>(&acc[mt][nn][h2]));
                *reinterpret_cast<uint32_t*>(
                    P.outh[z] + (size_t)rr2 * NN + col) =
                    pkh(vv.x + b0, vv.y + b1);
            }
        }
    }
}

// ---------------------------------------------------------------------------
// h += ctx (fp16); then LN -> fp16 x1.  (post-attention residual + LN2)
// ---------------------------------------------------------------------------
__global__ void k_lnadd(const __half* __restrict__ ctx,
                        float* __restrict__ h,
                        const float* __restrict__ gam,
                        const float* __restrict__ bet,
                        __half* __restrict__ oh) {
    const int row = blockIdx.x;
    const int t = threadIdx.x;
    const size_t base = (size_t)row * Hh;
    float v[3];
    float s = 0.f, sq = 0.f;
#pragma unroll
    for (int j = 0; j < 3; j++) {
        int c = t + j * 256;
        float val = h[base + c] + __half2float(ctx[base + c]);
        h[base + c] = val;
        v[j] = val;
        s += val;
        sq += val * val;
    }
#pragma unroll
    for (int o = 16; o; o >>= 1) {
        s  += __shfl_xor_sync(0xffffffffu, s,  o);
        sq += __shfl_xor_sync(0xffffffffu, sq, o);
    }
    __shared__ float ss[8], sv[8];
    if ((t & 31) == 0) { ss[t >> 5] = s; sv[t >> 5] = sq; }
    __syncthreads();
    __shared__ float bm, br;
    if (t == 0) {
        float ts = 0.f, tq = 0.f;
#pragma unroll
        for (int i = 0; i < 8; i++) { ts += ss[i]; tq += sv[i]; }
        float mean = ts * (1.0f / Hh);
        float var  = tq * (1.0f / Hh) - mean * mean;
        bm = mean;
        br = rsqrtf(var + EPSf);
    }
    __syncthreads();
    const float mean = bm, rstd = br;
#pragma unroll
    for (int j = 0; j < 3; j++) {
        int c = t + j * 256;
        float val = (v[j] - mean) * rstd * gam[c] + bet[c];
        oh[base + c] = __float2half_rn(val);
    }
}

// ---------------------------------------------------------------------------
// split-K reduce (fp16 partials, +bias +residual) fused with NEXT layer's LN.
// ---------------------------------------------------------------------------
__global__ void k_redln(const __half* __restrict__ p0, const __half* __restrict__ p1,
                        const __half* __restrict__ p2, const float* __restrict__ bias,
                        float* __restrict__ h,
                        const float* __restrict__ gam, const float* __restrict__ bet,
                        __half* __restrict__ oh) {
    const int row = blockIdx.x;
    const int t = threadIdx.x;
    const size_t base = (size_t)row * Hh;
    float v[3];
    float s = 0.f, sq = 0.f;
#pragma unroll
    for (int j = 0; j < 3; j++) {
        int c = t + j * 256;
        float val = h[base + c] + __half2float(p0[base + c]) +
                    __half2float(p1[base + c]) + __half2float(p2[base + c]) +
                    bias[c];
        h[base + c] = val;
        v[j] = val;
        s += val;
        sq += val * val;
    }
#pragma unroll
    for (int o = 16; o; o >>= 1) {
        s  += __shfl_xor_sync(0xffffffffu, s,  o);
        sq += __shfl_xor_sync(0xffffffffu, sq, o);
    }
    __shared__ float ss[8], sv[8];
    if ((t & 31) == 0) { ss[t >> 5] = s; sv[t >> 5] = sq; }
    __syncthreads();
    __shared__ float bm, br;
    if (t == 0) {
        float ts = 0.f, tq = 0.f;
#pragma unroll
        for (int i = 0; i < 8; i++) { ts += ss[i]; tq += sv[i]; }
        float mean = ts * (1.0f / Hh);
        float var  = tq * (1.0f / Hh) - mean * mean;
        bm = mean;
        br = rsqrtf(var + EPSf);
    }
    __syncthreads();
    const float mean = bm, rstd = br;
#pragma unroll
    for (int j = 0; j < 3; j++) {
        int c = t + j * 256;
        float val = (v[j] - mean) * rstd * gam[c] + bet[c];
        oh[base + c] = __float2half_rn(val);
    }
}

// last layer: reduce + final LN -> fp32 out
__global__ void k_redlnf(const __half* __restrict__ p0, const __half* __restrict__ p1,
                         const __half* __restrict__ p2, const float* __restrict__ bias,
                         const float* __restrict__ h,
                         const float* __restrict__ gam, const float* __restrict__ bet,
                         float* __restrict__ out) {
    const int row = blockIdx.x;
    const int t = threadIdx.x;
    const size_t base = (size_t)row * Hh;
    float v[3];
    float s = 0.f, sq = 0.f;
#pragma unroll
    for (int j = 0; j < 3; j++) {
        int c = t + j * 256;
        float val = h[base + c] + __half2float(p0[base + c]) +
                    __half2float(p1[base + c]) + __half2float(p2[base + c]) +
                    bias[c];
        v[j] = val;
        s += val;
        sq += val * val;
    }
#pragma unroll
    for (int o = 16; o; o >>= 1) {
        s  += __shfl_xor_sync(0xffffffffu, s,  o);
        sq += __shfl_xor_sync(0xffffffffu, sq, o);
    }
    __shared__ float ss[8], sv[8];
    if ((t & 31) == 0) { ss[t >> 5] = s; sv[t >> 5] = sq; }
    __syncthreads();
    __shared__ float bm, br;
    if (t == 0) {
        float ts = 0.f, tq = 0.f;
#pragma unroll
        for (int i = 0; i < 8; i++) { ts += ss[i]; tq += sv[i]; }
        float mean = ts * (1.0f / Hh);
        float var  = tq * (1.0f / Hh) - mean * mean;
        bm = mean;
        br = rsqrtf(var + EPSf);
    }
    __syncthreads();
    const float mean = bm, rstd = br;
#pragma unroll
    for (int j = 0; j < 3; j++) {
        int c = t + j * 256;
        out[base + c] = (v[j] - mean) * rstd * gam[c] + bet[c];
    }
}

// ---------------------------------------------------------------------------
// Fused: h = hidden + pos; LN1(layer 0) -> fp16 x1
// ---------------------------------------------------------------------------
__global__ void k_addposln(const float* __restrict__ hid,
                           const float* __restrict__ pos,
                           float* __restrict__ h,
                           const float* __restrict__ gam,
                           const float* __restrict__ bet,
                           __half* __restrict__ oh) {
    const int row = blockIdx.x;          // b*Ss + s
    const int t = threadIdx.x;
    const size_t base = (size_t)row * Hh;
    const size_t pbase = (size_t)(row & (Ss - 1)) * Hh;
    float v[3];
    float s = 0.f, sq = 0.f;
#pragma unroll
    for (int j = 0; j < 3; j++) {
        int c = t + j * 256;
        float val = hid[base + c] + pos[pbase + c];
        h[base + c] = val;
        v[j] = val;
        s += val;
        sq += val * val;
    }
#pragma unroll
    for (int o = 16; o; o >>= 1) {
        s  += __shfl_xor_sync(0xffffffffu, s,  o);
        sq += __shfl_xor_sync(0xffffffffu, sq, o);
    }
    __shared__ float ss[8], sv[8];
    if ((t & 31) == 0) { ss[t >> 5] = s; sv[t >> 5] = sq; }
    __syncthreads();
    __shared__ float bm, br;
    if (t == 0) {
        float ts = 0.f, tq = 0.f;
#pragma unroll
        for (int i = 0; i < 8; i++) { ts += ss[i]; tq += sv[i]; }
        float mean = ts * (1.0f / Hh);
        float var  = tq * (1.0f / Hh) - mean * mean;
        bm = mean;
        br = rsqrtf(var + EPSf);
    }
    __syncthreads();
    const float mean = bm, rstd = br;
#pragma unroll
    for (int j = 0; j < 3; j++) {
        int c = t + j * 256;
        float val = (v[j] - mean) * rstd * gam[c] + bet[c];
        oh[base + c] = __float2half_rn(val);
    }
}

// ---------------------------------------------------------------------------
// Flash attention — occ 2, Q hoisted to registers, fixed-max softmax,
// 3-stage KV ring, 1 sync/tile, fp16 ctx output. (R14 champion config)
// ---------------------------------------------------------------------------
#define FRB 144
#define SQ0 0
#define SKV0 18432
#define KVSTG 18432
#define SMB (SKV0 + 3*KVSTG)
#define FL_SMEM (SMB + 2048)

__device__ __forceinline__ void flash_issue_kv(
    uint32_t base, const __half* K1, const __half* V1,
    int b, int hh, int kt, int tid) {
    int r = tid >> 2, cpart = tid & 3;
    size_t g = ((size_t)(b * Ss + kt * 64 + r)) * Hh + hh * DHh + cpart * 16;
    uint32_t so = (uint32_t)r * FRB + cpart * 32;
    cp16(base + so,         K1 + g); cp16(base + so + 16,        K1 + g + 8);
    cp16(base + 9216 + so,  V1 + g); cp16(base + 9216 + so + 16, V1 + g + 8);
}

__global__ void __launch_bounds__(256, 2) k_flash(
    const __half* __restrict__ Q1,
    const __half* __restrict__ K1,
    const __half* __restrict__ V1,
    const int* __restrict__ mask, __half* __restrict__ CTX) {
    extern __shared__ char smem[];
    const int bh = blockIdx.y;
    const int b = bh / NHh, hh = bh - b * NHh;
    const int q0 = blockIdx.x * 128;
    const uint32_t sb = smem_u32(smem);
    const int tid = threadIdx.x, wid = tid >> 5, lane = tid & 31;
    const float scale = 0.125f;

    {
        int r = tid >> 1, cpart = tid & 1;
        size_t g = ((size_t)(b * Ss + q0 + r)) * Hh + hh * DHh + cpart * 32;
        uint32_t so = (uint32_t)r * FRB + cpart * 64;
#pragma unroll
        for (int i = 0; i < 4; i++)
            cp16(sb + SQ0 + so + 16 * i, Q1 + g + 8 * i);
    }
    flash_issue_kv(sb + SKV0, K1, V1, b, hh, 0, tid);
    cp_commit();
    flash_issue_kv(sb + SKV0 + KVSTG, K1, V1, b, hh, 1, tid);
    cp_commit();

#pragma unroll
    for (int i = 0; i < 4; i++) {
        int kx = tid + i * 256;
        float mb = (mask[b * Ss + kx] == 0) ? -10000.0f : 0.0f;
        *reinterpret_cast<__half*>(smem + SMB + kx * 2) = __float2half_rn(mb);
    }

    float O[8][4];
#pragma unroll
    for (int i = 0; i < 8; i++)
#pragma unroll
        for (int j = 0; j < 4; j++) O[i][j] = 0.f;
    float l0 = 0.f, l1 = 0.f;

    const uint32_t aoff = (uint32_t)(16 * wid + (lane & 15)) * FRB +
                          ((lane >> 4) & 1) * 16;
    const uint32_t koff = (uint32_t)(((lane >> 4) << 3) + (lane & 7)) * FRB +
                          ((lane >> 3) & 1) * 16;
    const uint32_t voff = (uint32_t)(lane & 15) * FRB + ((lane >> 4) & 1) * 16;

    // hoist Q fragments to registers
    uint32_t qf[4][4];
    cp_wait1();
    __syncthreads();
#pragma unroll
    for (int s = 0; s < 4; s++)
        LDMX4(qf[s], sb + SQ0 + aoff + s * 32);

    for (int kt = 0; kt < 16; kt++) {
        const uint32_t kv = sb + SKV0 + (uint32_t)(kt % 3) * KVSTG;
        if (kt) {
            cp_wait1();
            __syncthreads();
        }
        if (kt + 2 < 16) {
            flash_issue_kv(sb + SKV0 + (uint32_t)((kt + 2) % 3) * KVSTG,
                           K1, V1, b, hh, kt + 2, tid);
            cp_commit();
        }

        uint32_t sh16[8][2];
#pragma unroll
        for (int i = 0; i < 8; i++) { sh16[i][0] = 0u; sh16[i][1] = 0u; }

#pragma unroll
        for (int s = 0; s < 4; s++) {
#pragma unroll
            for (int jp = 0; jp < 4; jp++) {
                uint32_t ka = kv + (uint32_t)(16 * jp) * FRB + koff + s * 32;
                uint32_t kh4[4];
                LDMX4(kh4, ka);
#pragma unroll
                for (int half = 0; half < 2; half++)
                    mmah16(sh16[2 * jp + half], qf[s],
                           kh4[half * 2], kh4[half * 2 + 1]);
            }
        }

        float sacc[8][4];
#pragma unroll
        for (int j = 0; j < 8; j++) {
            float2 s01 = __half22float2(
                *reinterpret_cast<const __half2*>(&sh16[j][0]));
            float2 s23 = __half22float2(
                *reinterpret_cast<const __half2*>(&sh16[j][1]));
            float2 mbv = __half22float2(*reinterpret_cast<const __half2*>(
                smem + SMB + (kt * 64 + 8 * j + 2 * (lane & 3)) * 2));
            float p0 = __expf(s01.x * scale + mbv.x);
            float p1 = __expf(s01.y * scale + mbv.y);
            float p2 = __expf(s23.x * scale + mbv.x);
            float p3 = __expf(s23.y * scale + mbv.y);
            sacc[j][0] = p0; sacc[j][1] = p1; sacc[j][2] = p2; sacc[j][3] = p3;
            l0 += p0 + p1; l1 += p2 + p3;
        }

#pragma unroll
        for (int s = 0; s < 4; s++) {
            uint32_t ph[4];
            ph[0] = pkh(sacc[2 * s][0],     sacc[2 * s][1]);
            ph[1] = pkh(sacc[2 * s][2],     sacc[2 * s][3]);
            ph[2] = pkh(sacc[2 * s + 1][0], sacc[2 * s + 1][1]);
            ph[3] = pkh(sacc[2 * s + 1][2], sacc[2 * s + 1][3]);
#pragma unroll
            for (int dp = 0; dp < 4; dp++) {
                uint32_t va = kv + 9216 + (uint32_t)(16 * s) * FRB + voff + dp * 32;
                uint32_t vh4[4];
                LDMX4T(vh4, va);
#pragma unroll
                for (int half = 0; half < 2; half++)
                    mmah(O[2 * dp + half], ph,
                         vh4[half * 2], vh4[half * 2 + 1]);
            }
        }
    }

    l0 += __shfl_xor_sync(0xffffffffu, l0, 1);
    l0 += __shfl_xor_sync(0xffffffffu, l0, 2);
    l1 += __shfl_xor_sync(0xffffffffu, l1, 1);
    l1 += __shfl_xor_sync(0xffffffffu, l1, 2);
    float i0 = 1.0f / l0, i1 = 1.0f / l1;
    int r0 = b * Ss + q0 + 16 * wid + (lane >> 2);
#pragma unroll
    for (int jd = 0; jd < 8; jd++) {
        int col = hh * DHh + 8 * jd + 2 * (lane & 3);
        *reinterpret_cast<uint32_t*>(&CTX[(size_t)r0 * Hh + col]) =
            pkh(O[jd][0] * i0, O[jd][1] * i0);
        *reinterpret_cast<uint32_t*>(&CTX[(size_t)(r0 + 8) * Hh + col]) =
            pkh(O[jd][2] * i1, O[jd][3] * i1);
    }
}

// ---------------------------------------------------------------------------
// Launch
// ---------------------------------------------------------------------------
extern "C" void kernel_launch(void* const* d_in, const int* in_sizes, int n_in,
                              void* d_out, int out_size) {
    const float* hid  = (const float*)d_in[0];
    const int*   mask = (const int*)  d_in[1];
    const float* pos  = (const float*)d_in[2];
    const float* Wq   = (const float*)d_in[3];
    const float* bq   = (const float*)d_in[4];
    const float* Wk   = (const float*)d_in[5];
    const float* bk   = (const float*)d_in[6];
    const float* Wv   = (const float*)d_in[7];
    const float* bv   = (const float*)d_in[8];
    const float* l1s  = (const float*)d_in[9];
    const float* l1b  = (const float*)d_in[10];
    const float* l2s  = (const float*)d_in[11];
    const float* l2b  = (const float*)d_in[12];
    const float* W1   = (const float*)d_in[13];
    const float* b1   = (const float*)d_in[14];
    const float* W2   = (const float*)d_in[15];
    const float* b2   = (const float*)d_in[16];
    const float* lnfs = (const float*)d_in[17];
    const float* lnfb = (const float*)d_in[18];
    float* out = (float*)d_out;

    float* h;
    __half *parth, *ctx;
    cudaGetSymbolAddress((void**)&h, g_h);
    cudaGetSymbolAddress((void**)&parth, g_parth);
    cudaGetSymbolAddress((void**)&ctx, g_ctx);

    __half *x1, *f1, *q1, *k1, *v1;
    cudaGetSymbolAddress((void**)&x1, g_x1);
    cudaGetSymbolAddress((void**)&f1, g_f1);
    cudaGetSymbolAddress((void**)&q1, g_q1);
    cudaGetSymbolAddress((void**)&k1, g_k1);
    cudaGetSymbolAddress((void**)&v1, g_v1);

    __half *wq, *wk, *wv, *w1, *w2;
    cudaGetSymbolAddress((void**)&wq, g_wqt);
    cudaGetSymbolAddress((void**)&wk, g_wkt);
    cudaGetSymbolAddress((void**)&wv, g_wvt);
    cudaGetSymbolAddress((void**)&w1, g_w1t);
    cudaGetSymbolAddress((void**)&w2, g_w2t);

    cudaFuncSetAttribute(k_mgemm<1>, cudaFuncAttributeMaxDynamicSharedMemorySize, MG_SMEM);
    cudaFuncSetAttribute(k_mgemm<4>, cudaFuncAttributeMaxDynamicSharedMemorySize, MG_SMEM);
    cudaFuncSetAttribute(k_mgemm16, cudaFuncAttributeMaxDynamicSharedMemorySize, MG_SMEM);
    cudaFuncSetAttribute(k_flash,    cudaFuncAttributeMaxDynamicSharedMemorySize, FL_SMEM);

    // weight transpose to fp16
    {
        dim3 blk(32, 8);
        k_wt<<<dim3(Hh / 32, Hh / 32, Ll), blk>>>(Wq, wq, Hh, Hh);
        k_wt<<<dim3(Hh / 32, Hh / 32, Ll), blk>>>(Wk, wk, Hh, Hh);
        k_wt<<<dim3(Hh / 32, Hh / 32, Ll), blk>>>(Wv, wv, Hh, Hh);
        k_wt<<<dim3(FFf / 32, Hh / 32, Ll), blk>>>(W1, w1, Hh, FFf);
        k_wt<<<dim3(Hh / 32, FFf / 32, Ll), blk>>>(W2, w2, FFf, Hh);
    }

    // fused: h = hidden + pos, LN1(layer 0) -> x1
    k_addposln<<<Mm, 256>>>(hid, pos, h, l1s, l1b, x1);

    for (int l = 0; l < Ll; l++) {
        const size_t wOff = (size_t)l * Hh * Hh;
        const size_t fOff = (size_t)l * Hh * FFf;

        // fused QKV (fp16 accum) -> fp16
        {
            GPtrs P = {};
            P.w[0] = wq + wOff; P.w[1] = wk + wOff; P.w[2] = wv + wOff;
            P.bias[0] = bq + l * Hh; P.bias[1] = bk + l * Hh; P.bias[2] = bv + l * Hh;
            P.outh[0] = q1; P.outh[1] = k1; P.outh[2] = v1;
            k_mgemm16<<<dim3(Hh / 128, Mm / 128, 3), 256, MG_SMEM>>>(
                x1, P, Hh, Hh, Hh);
        }

        // flash -> fp16 ctx
        k_flash<<<dim3(Ss / 128, Bb * NHh), 256, FL_SMEM>>>(
            q1, k1, v1, mask, ctx);

        // h += ctx; LN2 -> x1
        k_lnadd<<<Mm, 256>>>(ctx, h, l2s + l * Hh, l2b + l * Hh, x1);

        // FFN1: GELU(x @ W1 + b1) -> fp16
        {
            GPtrs P = {};
            P.w[0] = w1 + fOff;
            P.bias[0] = b1 + l * FFf;
            P.outh[0] = f1;
            k_mgemm<1><<<dim3(FFf / 128, Mm / 128, 1), 256, MG_SMEM>>>(
                x1, P, Hh, Hh, FFf);
        }
        // FFN2 split-K x3 partials (fp16)
        {
            GPtrs P = {};
            P.w[0] = w2 + fOff;        P.w[1] = w2 + fOff + 1024;
            P.w[2] = w2 + fOff + 2048;
            P.aoff[0] = 0; P.aoff[1] = 1024; P.aoff[2] = 2048;
            P.outh[0] = parth;
            P.outh[1] = parth + (size_t)Mm * Hh;
            P.outh[2] = parth + 2 * (size_t)Mm * Hh;
            k_mgemm<4><<<dim3(Hh / 128, Mm / 128, 3), 256, MG_SMEM>>>(
                f1, P, 1024, FFf, Hh);
        }
        // reduce + residual, fused with next LN1 (or final LN on last layer)
        if (l + 1 < Ll) {
            k_redln<<<Mm, 256>>>(
                parth, parth + (size_t)Mm * Hh, parth + 2 * (size_t)Mm * Hh,
                b2 + l * Hh, h, l1s + (l + 1) * Hh, l1b + (l + 1) * Hh, x1);
        } else {
            k_redlnf<<<Mm, 256>>>(
                parth, parth + (size_t)Mm * Hh, parth + 2 * (size_t)Mm * Hh,
                b2 + l * Hh, h, lnfs, lnfb, out);
        }
    }
}

// round 17
// speedup vs baseline: 1.0165x; 1.0109x over previous
#include <cuda_runtime.h>
#include <cuda_fp16.h>
#include <math.h>
#include <stdint.h>

// ---------------------------------------------------------------------------
// HuBERT transformer encoder — fp16 mma.sync GEMMs (3-stage ring, fp16
// split-K partials), flash attention (occ-2, Q-in-regs, fixed-max softmax,
// fp16 ctx output), vectorized fused residual/LN kernels.
// B=4 S=1024 H=768 L=12 NH=12 DH=64 FF=3072
// ---------------------------------------------------------------------------

#define Bb 4
#define Ss 1024
#define Hh 768
#define Ll 12
#define NHh 12
#define DHh 64
#define FFf 3072
#define Mm (Bb*Ss)
#define EPSf 1e-5f

// ---------------- scratch ----------------------------------------------------
__device__ float g_h[Mm*Hh];
__device__ __half g_parth[3][Mm*Hh];
__device__ __half g_ctx[Mm*Hh];

__device__ __half g_x1[Mm*Hh];
__device__ __half g_f1[(size_t)Mm*FFf];
__device__ __half g_q1[Mm*Hh];
__device__ __half g_k1[Mm*Hh];
__device__ __half g_v1[Mm*Hh];

__device__ __half g_wqt[Ll*Hh*Hh];
__device__ __half g_wkt[Ll*Hh*Hh];
__device__ __half g_wvt[Ll*Hh*Hh];
__device__ __half g_w1t[Ll*FFf*Hh];
__device__ __half g_w2t[Ll*FFf*Hh];

// ---------------- PTX helpers ------------------------------------------------
__device__ __forceinline__ uint32_t smem_u32(const void* p) {
    uint32_t a;
    asm("{ .reg .u64 t; cvta.to.shared.u64 t, %1; cvt.u32.u64 %0, t; }"
        : "=r"(a) : "l"(p));
    return a;
}
__device__ __forceinline__ void cp16(uint32_t sa, const void* g) {
    asm volatile("cp.async.cg.shared.global [%0], [%1], 16;"
                 :: "r"(sa), "l"(g) : "memory");
}
__device__ __forceinline__ void cp_commit() {
    asm volatile("cp.async.commit_group;" ::: "memory");
}
__device__ __forceinline__ void cp_wait1() {
    asm volatile("cp.async.wait_group 1;" ::: "memory");
}
#define LDMX4(R, addr) \
    asm volatile("ldmatrix.sync.aligned.m8n8.x4.shared.b16 {%0,%1,%2,%3}, [%4];" \
        : "=r"((R)[0]), "=r"((R)[1]), "=r"((R)[2]), "=r"((R)[3]) : "r"(addr))
#define LDMX4T(R, addr) \
    asm volatile("ldmatrix.sync.aligned.m8n8.x4.trans.shared.b16 {%0,%1,%2,%3}, [%4];" \
        : "=r"((R)[0]), "=r"((R)[1]), "=r"((R)[2]), "=r"((R)[3]) : "r"(addr))

__device__ __forceinline__ void mmah(float* c, const uint32_t* a,
                                     uint32_t b0, uint32_t b1) {
    asm volatile(
        "mma.sync.aligned.m16n8k16.row.col.f32.f16.f16.f32 "
        "{%0,%1,%2,%3}, {%4,%5,%6,%7}, {%8,%9}, {%0,%1,%2,%3};"
        : "+f"(c[0]), "+f"(c[1]), "+f"(c[2]), "+f"(c[3])
        : "r"(a[0]), "r"(a[1]), "r"(a[2]), "r"(a[3]), "r"(b0), "r"(b1));
}
__device__ __forceinline__ void mmah16(uint32_t* d, const uint32_t* a,
                                       uint32_t b0, uint32_t b1) {
    asm volatile(
        "mma.sync.aligned.m16n8k16.row.col.f16.f16.f16.f16 "
        "{%0,%1}, {%2,%3,%4,%5}, {%6,%7}, {%0,%1};"
        : "+r"(d[0]), "+r"(d[1])
        : "r"(a[0]), "r"(a[1]), "r"(a[2]), "r"(a[3]), "r"(b0), "r"(b1));
}
__device__ __forceinline__ uint32_t pkh(float f0, float f1) {
    __half2 h = __floats2half2_rn(f0, f1);
    return *reinterpret_cast<uint32_t*>(&h);
}

// ---------------------------------------------------------------------------
// Weight transpose to fp16: W[K,N] fp32 -> T[N,K] fp16. 64x64 tile, 256 thr,
// float4 loads + uint4 stores.
// ---------------------------------------------------------------------------
__global__ void k_wt(const float* __restrict__ W,
                     __half* __restrict__ T, int K, int N) {
    __shared__ float t[64][65];
    const size_t off = (size_t)blockIdx.z * K * N;
    const int n0 = blockIdx.x * 64, k0 = blockIdx.y * 64;
    const int tid = threadIdx.x;

    // load 64(k) x 64(n) fp32 tile via float4 (16 f4 per k-row)
#pragma unroll
    for (int p = 0; p < 4; p++) {
        int i = tid + p * 256;
        int kr = i >> 4, c4 = (i & 15) << 2;
        float4 v = *reinterpret_cast<const float4*>(
            &W[off + (size_t)(k0 + kr) * N + n0 + c4]);
        t[kr][c4 + 0] = v.x; t[kr][c4 + 1] = v.y;
        t[kr][c4 + 2] = v.z; t[kr][c4 + 3] = v.w;
    }
    __syncthreads();

    // store 64(n) x 64(k) fp16 via uint4 (8 u4 per n-row)
#pragma unroll
    for (int p = 0; p < 2; p++) {
        int i = tid + p * 256;
        int nr = i >> 3, seg = (i & 7) << 3;
        __half hb[8];
#pragma unroll
        for (int j = 0; j < 8; j++)
            hb[j] = __float2half_rn(t[seg + j][nr]);
        *reinterpret_cast<uint4*>(
            &T[off + (size_t)(n0 + nr) * K + k0 + seg]) =
            *reinterpret_cast<uint4*>(hb);
    }
}

// ---------------------------------------------------------------------------
// Shared GEMM plumbing — 3-stage cp.async ring
// ---------------------------------------------------------------------------
#define ROWB 144
#define STG  36864
#define MG_SMEM (3*STG)

struct GPtrs {
    const __half* w[3];
    const float* bias[3];
    __half* outh[3];
    int aoff[3];
};

__device__ __forceinline__ void issue_chunk(
    uint32_t s0, const __half* A, const __half* B,
    int m0, int n0, int LDK, int cc, int r, int cpart) {
    size_t ka = (size_t)(m0 + r) * LDK + cc * 64 + cpart * 32;
    size_t kb = (size_t)(n0 + r) * LDK + cc * 64 + cpart * 32;
    uint32_t so = (uint32_t)r * ROWB + cpart * 64;
#pragma unroll
    for (int i = 0; i < 4; i++) {
        cp16(s0 + so + 16 * i,         A + ka + 8 * i);
        cp16(s0 + 18432 + so + 16 * i, B + kb + 8 * i);
    }
}

// ---------------------------------------------------------------------------
// fp32-accum GEMM. EPI: 1 bias+GELU->fp16, 4 raw->fp16 partial (split-K)
// ---------------------------------------------------------------------------
template <int EPI>
__global__ void __launch_bounds__(256, 2) k_mgemm(
    const __half* __restrict__ A0, GPtrs P, int KK, int LDK, int NN) {
    extern __shared__ char smem[];
    const int z = blockIdx.z;
    const __half* __restrict__ A = A0 + P.aoff[z];
    const __half* __restrict__ B = P.w[z];

    const int m0 = blockIdx.y << 7, n0 = blockIdx.x << 7;
    const uint32_t sb = smem_u32(smem);
    const int tid = threadIdx.x;
    const int wid = tid >> 5, lane = tid & 31;
    const int wm = (wid >> 2) * 64;
    const int wn = (wid & 3) * 32;

    const int r = tid >> 1, cpart = tid & 1;
    const int NCH = KK / 64;

    float acc[4][4][4];
#pragma unroll
    for (int i = 0; i < 4; i++)
#pragma unroll
        for (int j = 0; j < 4; j++)
#pragma unroll
            for (int k = 0; k < 4; k++) acc[i][j][k] = 0.f;

    issue_chunk(sb,       A, B, m0, n0, LDK, 0, r, cpart); cp_commit();
    issue_chunk(sb + STG, A, B, m0, n0, LDK, 1, r, cpart); cp_commit();

    const uint32_t aoff = (uint32_t)(lane & 15) * ROWB + (lane >> 4) * 16;
    const uint32_t boff = (uint32_t)(((lane >> 4) << 3) + (lane & 7)) * ROWB +
                          ((lane >> 3) & 1) * 16;

    int rd = 0, wr = 2;
    for (int ch = 0; ch < NCH; ch++) {
        const uint32_t s0 = sb + (uint32_t)rd * STG;
        cp_wait1();
        __syncthreads();
        if (ch + 2 < NCH) {
            issue_chunk(sb + (uint32_t)wr * STG, A, B, m0, n0, LDK,
                        ch + 2, r, cpart);
            cp_commit();
        }

#pragma unroll
        for (int ks = 0; ks < 4; ks++) {
            uint32_t bh[2][4];
#pragma unroll
            for (int np = 0; np < 2; np++) {
                uint32_t ad = s0 + 18432 + (uint32_t)(wn + np * 16) * ROWB +
                              boff + ks * 32;
                LDMX4(bh[np], ad);
            }
#pragma unroll
            for (int mt = 0; mt < 4; mt++) {
                uint32_t ad = s0 + (uint32_t)(wm + mt * 16) * ROWB + aoff + ks * 32;
                uint32_t ah[4];
                LDMX4(ah, ad);
#pragma unroll
                for (int nn = 0; nn < 4; nn++) {
                    uint32_t b0 = bh[nn >> 1][(nn & 1) * 2];
                    uint32_t b1 = bh[nn >> 1][(nn & 1) * 2 + 1];
                    mmah(acc[mt][nn], ah, b0, b1);
                }
            }
        }
        rd = (rd == 2) ? 0 : rd + 1;
        wr = (wr == 2) ? 0 : wr + 1;
    }

#pragma unroll
    for (int mt = 0; mt < 4; mt++) {
#pragma unroll
        for (int nn = 0; nn < 4; nn++) {
            int row = m0 + wm + mt * 16 + (lane >> 2);
            int col = n0 + wn + nn * 8 + (lane & 3) * 2;
            float b0 = (EPI == 4) ? 0.f : P.bias[z][col];
            float b1 = (EPI == 4) ? 0.f : P.bias[z][col + 1];
#pragma unroll
            for (int h2 = 0; h2 < 2; h2++) {
                int rr2 = row + h2 * 8;
                float v0 = acc[mt][nn][h2 * 2]     + b0;
                float v1 = acc[mt][nn][h2 * 2 + 1] + b1;
                if (EPI == 1) {
                    v0 = 0.5f * v0 * (1.0f + erff(v0 * 0.70710678118654752f));
                    v1 = 0.5f * v1 * (1.0f + erff(v1 * 0.70710678118654752f));
                }
                *reinterpret_cast<uint32_t*>(
                    P.outh[z] + (size_t)rr2 * NN + col) = pkh(v0, v1);
            }
        }
    }
}

// ---------------------------------------------------------------------------
// fp16-accum GEMM (QKV): bias -> fp16 out
// ---------------------------------------------------------------------------
__global__ void __launch_bounds__(256, 2) k_mgemm16(
    const __half* __restrict__ A, GPtrs P, int KK, int LDK, int NN) {
    extern __shared__ char smem[];
    const int z = blockIdx.z;
    const __half* __restrict__ B = P.w[z];

    const int m0 = blockIdx.y << 7, n0 = blockIdx.x << 7;
    const uint32_t sb = smem_u32(smem);
    const int tid = threadIdx.x;
    const int wid = tid >> 5, lane = tid & 31;
    const int wm = (wid >> 2) * 64;
    const int wn = (wid & 3) * 32;

    const int r = tid >> 1, cpart = tid & 1;
    const int NCH = KK / 64;

    uint32_t acc[4][4][2];
#pragma unroll
    for (int i = 0; i < 4; i++)
#pragma unroll
        for (int j = 0; j < 4; j++) { acc[i][j][0] = 0u; acc[i][j][1] = 0u; }

    issue_chunk(sb,       A, B, m0, n0, LDK, 0, r, cpart); cp_commit();
    issue_chunk(sb + STG, A, B, m0, n0, LDK, 1, r, cpart); cp_commit();

    const uint32_t aoff = (uint32_t)(lane & 15) * ROWB + (lane >> 4) * 16;
    const uint32_t boff = (uint32_t)(((lane >> 4) << 3) + (lane & 7)) * ROWB +
                          ((lane >> 3) & 1) * 16;

    int rd = 0, wr = 2;
    for (int ch = 0; ch < NCH; ch++) {
        const uint32_t s0 = sb + (uint32_t)rd * STG;
        cp_wait1();
        __syncthreads();
        if (ch + 2 < NCH) {
            issue_chunk(sb + (uint32_t)wr * STG, A, B, m0, n0, LDK,
                        ch + 2, r, cpart);
            cp_commit();
        }

#pragma unroll
        for (int ks = 0; ks < 4; ks++) {
            uint32_t bh[2][4];
#pragma unroll
            for (int np = 0; np < 2; np++) {
                uint32_t ad = s0 + 18432 + (uint32_t)(wn + np * 16) * ROWB +
                              boff + ks * 32;
                LDMX4(bh[np], ad);
            }
#pragma unroll
            for (int mt = 0; mt < 4; mt++) {
                uint32_t ad = s0 + (uint32_t)(wm + mt * 16) * ROWB + aoff + ks * 32;
                uint32_t ah[4];
                LDMX4(ah, ad);
#pragma unroll
                for (int nn = 0; nn < 4; nn++) {
                    uint32_t b0 = bh[nn >> 1][(nn & 1) * 2];
                    uint32_t b1 = bh[nn >> 1][(nn & 1) * 2 + 1];
                    mmah16(acc[mt][nn], ah, b0, b1);
                }
            }
        }
        rd = (rd == 2) ? 0 : rd + 1;
        wr = (wr == 2) ? 0 : wr + 1;
    }

#pragma unroll
    for (int mt = 0; mt < 4; mt++) {
#pragma unroll
        for (int nn = 0; nn < 4; nn++) {
            int row = m0 + wm + mt * 16 + (lane >> 2);
            int col = n0 + wn + nn * 8 + (lane & 3) * 2;
            float b0 = P.bias[z][col], b1 = P.bias[z][col + 1];
#pragma unroll
            for (int h2 = 0; h2 < 2; h2++) {
                int rr2 = row + h2 * 8;
                float2 vv = __half22float2(
                    *reinterpret_cast<const __half2*>(&acc[mt][nn][h2]));
                *reinterpret_cast<uint32_t*>(
                    P.outh[z] + (size_t)rr2 * NN + col) =
                    pkh(vv.x + b0, vv.y + b1);
            }
        }
    }
}

// ---------------------------------------------------------------------------
// Vectorized row-glue kernels. 192 threads/row, 4 contiguous elems/thread.
// Common LN tail shared via macro-free inline pattern.
// ---------------------------------------------------------------------------
__device__ __forceinline__ float2 ldh2(const __half* p) {
    return __half22float2(*reinterpret_cast<const __half2*>(p));
}

// h += ctx (fp16); LN -> fp16 x1
__global__ void __launch_bounds__(192) k_lnadd(
    const __half* __restrict__ ctx, float* __restrict__ h,
    const float* __restrict__ gam, const float* __restrict__ bet,
    __half* __restrict__ oh) {
    const int row = blockIdx.x, t = threadIdx.x;
    const size_t base = (size_t)row * Hh;
    const int c = t * 4;
    float4 hv = *reinterpret_cast<const float4*>(&h[base + c]);
    float2 c0 = ldh2(&ctx[base + c]), c1 = ldh2(&ctx[base + c + 2]);
    float v[4] = {hv.x + c0.x, hv.y + c0.y, hv.z + c1.x, hv.w + c1.y};
    *reinterpret_cast<float4*>(&h[base + c]) =
        make_float4(v[0], v[1], v[2], v[3]);
    float s = v[0] + v[1] + v[2] + v[3];
    float sq = v[0]*v[0] + v[1]*v[1] + v[2]*v[2] + v[3]*v[3];
#pragma unroll
    for (int o = 16; o; o >>= 1) {
        s  += __shfl_xor_sync(0xffffffffu, s,  o);
        sq += __shfl_xor_sync(0xffffffffu, sq, o);
    }
    __shared__ float ss[6], sv[6];
    if ((t & 31) == 0) { ss[t >> 5] = s; sv[t >> 5] = sq; }
    __syncthreads();
    __shared__ float bm, br;
    if (t == 0) {
        float ts = 0.f, tq = 0.f;
#pragma unroll
        for (int i = 0; i < 6; i++) { ts += ss[i]; tq += sv[i]; }
        float mean = ts * (1.0f / Hh);
        bm = mean;
        br = rsqrtf(tq * (1.0f / Hh) - mean * mean + EPSf);
    }
    __syncthreads();
    const float mean = bm, rstd = br;
    float4 g4 = *reinterpret_cast<const float4*>(&gam[c]);
    float4 b4 = *reinterpret_cast<const float4*>(&bet[c]);
    uint2 o2;
    o2.x = pkh((v[0]-mean)*rstd*g4.x + b4.x, (v[1]-mean)*rstd*g4.y + b4.y);
    o2.y = pkh((v[2]-mean)*rstd*g4.z + b4.z, (v[3]-mean)*rstd*g4.w + b4.w);
    *reinterpret_cast<uint2*>(&oh[base + c]) = o2;
}

// split-K reduce (+bias +residual) fused with NEXT layer's LN
__global__ void __launch_bounds__(192) k_redln(
    const __half* __restrict__ p0, const __half* __restrict__ p1,
    const __half* __restrict__ p2, const float* __restrict__ bias,
    float* __restrict__ h,
    const float* __restrict__ gam, const float* __restrict__ bet,
    __half* __restrict__ oh) {
    const int row = blockIdx.x, t = threadIdx.x;
    const size_t base = (size_t)row * Hh;
    const int c = t * 4;
    float4 hv = *reinterpret_cast<const float4*>(&h[base + c]);
    float2 a0 = ldh2(&p0[base + c]), a1 = ldh2(&p0[base + c + 2]);
    float2 d0 = ldh2(&p1[base + c]), d1 = ldh2(&p1[base + c + 2]);
    float2 e0 = ldh2(&p2[base + c]), e1 = ldh2(&p2[base + c + 2]);
    float4 bs = *reinterpret_cast<const float4*>(&bias[c]);
    float v[4];
    v[0] = hv.x + a0.x + d0.x + e0.x + bs.x;
    v[1] = hv.y + a0.y + d0.y + e0.y + bs.y;
    v[2] = hv.z + a1.x + d1.x + e1.x + bs.z;
    v[3] = hv.w + a1.y + d1.y + e1.y + bs.w;
    *reinterpret_cast<float4*>(&h[base + c]) =
        make_float4(v[0], v[1], v[2], v[3]);
    float s = v[0] + v[1] + v[2] + v[3];
    float sq = v[0]*v[0] + v[1]*v[1] + v[2]*v[2] + v[3]*v[3];
#pragma unroll
    for (int o = 16; o; o >>= 1) {
        s  += __shfl_xor_sync(0xffffffffu, s,  o);
        sq += __shfl_xor_sync(0xffffffffu, sq, o);
    }
    __shared__ float ss[6], sv[6];
    if ((t & 31) == 0) { ss[t >> 5] = s; sv[t >> 5] = sq; }
    __syncthreads();
    __shared__ float bm, br;
    if (t == 0) {
        float ts = 0.f, tq = 0.f;
#pragma unroll
        for (int i = 0; i < 6; i++) { ts += ss[i]; tq += sv[i]; }
        float mean = ts * (1.0f / Hh);
        bm = mean;
        br = rsqrtf(tq * (1.0f / Hh) - mean * mean + EPSf);
    }
    __syncthreads();
    const float mean = bm, rstd = br;
    float4 g4 = *reinterpret_cast<const float4*>(&gam[c]);
    float4 b4 = *reinterpret_cast<const float4*>(&bet[c]);
    uint2 o2;
    o2.x = pkh((v[0]-mean)*rstd*g4.x + b4.x, (v[1]-mean)*rstd*g4.y + b4.y);
    o2.y = pkh((v[2]-mean)*rstd*g4.z + b4.z, (v[3]-mean)*rstd*g4.w + b4.w);
    *reinterpret_cast<uint2*>(&oh[base + c]) = o2;
}

// last layer: reduce + final LN -> fp32 out
__global__ void __launch_bounds__(192) k_redlnf(
    const __half* __restrict__ p0, const __half* __restrict__ p1,
    const __half* __restrict__ p2, const float* __restrict__ bias,
    const float* __restrict__ h,
    const float* __restrict__ gam, const float* __restrict__ bet,
    float* __restrict__ out) {
    const int row = blockIdx.x, t = threadIdx.x;
    const size_t base = (size_t)row * Hh;
    const int c = t * 4;
    float4 hv = *reinterpret_cast<const float4*>(&h[base + c]);
    float2 a0 = ldh2(&p0[base + c]), a1 = ldh2(&p0[base + c + 2]);
    float2 d0 = ldh2(&p1[base + c]), d1 = ldh2(&p1[base + c + 2]);
    float2 e0 = ldh2(&p2[base + c]), e1 = ldh2(&p2[base + c + 2]);
    float4 bs = *reinterpret_cast<const float4*>(&bias[c]);
    float v[4];
    v[0] = hv.x + a0.x + d0.x + e0.x + bs.x;
    v[1] = hv.y + a0.y + d0.y + e0.y + bs.y;
    v[2] = hv.z + a1.x + d1.x + e1.x + bs.z;
    v[3] = hv.w + a1.y + d1.y + e1.y + bs.w;
    float s = v[0] + v[1] + v[2] + v[3];
    float sq = v[0]*v[0] + v[1]*v[1] + v[2]*v[2] + v[3]*v[3];
#pragma unroll
    for (int o = 16; o; o >>= 1) {
        s  += __shfl_xor_sync(0xffffffffu, s,  o);
        sq += __shfl_xor_sync(0xffffffffu, sq, o);
    }
    __shared__ float ss[6], sv[6];
    if ((t & 31) == 0) { ss[t >> 5] = s; sv[t >> 5] = sq; }
    __syncthreads();
    __shared__ float bm, br;
    if (t == 0) {
        float ts = 0.f, tq = 0.f;
#pragma unroll
        for (int i = 0; i < 6; i++) { ts += ss[i]; tq += sv[i]; }
        float mean = ts * (1.0f / Hh);
        bm = mean;
        br = rsqrtf(tq * (1.0f / Hh) - mean * mean + EPSf);
    }
    __syncthreads();
    const float mean = bm, rstd = br;
    float4 g4 = *reinterpret_cast<const float4*>(&gam[c]);
    float4 b4 = *reinterpret_cast<const float4*>(&bet[c]);
    *reinterpret_cast<float4*>(&out[base + c]) = make_float4(
        (v[0]-mean)*rstd*g4.x + b4.x, (v[1]-mean)*rstd*g4.y + b4.y,
        (v[2]-mean)*rstd*g4.z + b4.z, (v[3]-mean)*rstd*g4.w + b4.w);
}

// fused: h = hidden + pos; LN1(layer 0) -> fp16 x1
__global__ void __launch_bounds__(192) k_addposln(
    const float* __restrict__ hid, const float* __restrict__ pos,
    float* __restrict__ h,
    const float* __restrict__ gam, const float* __restrict__ bet,
    __half* __restrict__ oh) {
    const int row = blockIdx.x, t = threadIdx.x;
    const size_t base = (size_t)row * Hh;
    const size_t pbase = (size_t)(row & (Ss - 1)) * Hh;
    const int c = t * 4;
    float4 hv = *reinterpret_cast<const float4*>(&hid[base + c]);
    float4 pv = *reinterpret_cast<const float4*>(&pos[pbase + c]);
    float v[4] = {hv.x + pv.x, hv.y + pv.y, hv.z + pv.z, hv.w + pv.w};
    *reinterpret_cast<float4*>(&h[base + c]) =
        make_float4(v[0], v[1], v[2], v[3]);
    float s = v[0] + v[1] + v[2] + v[3];
    float sq = v[0]*v[0] + v[1]*v[1] + v[2]*v[2] + v[3]*v[3];
#pragma unroll
    for (int o = 16; o; o >>= 1) {
        s  += __shfl_xor_sync(0xffffffffu, s,  o);
        sq += __shfl_xor_sync(0xffffffffu, sq, o);
    }
    __shared__ float ss[6], sv[6];
    if ((t & 31) == 0) { ss[t >> 5] = s; sv[t >> 5] = sq; }
    __syncthreads();
    __shared__ float bm, br;
    if (t == 0) {
        float ts = 0.f, tq = 0.f;
#pragma unroll
        for (int i = 0; i < 6; i++) { ts += ss[i]; tq += sv[i]; }
        float mean = ts * (1.0f / Hh);
        bm = mean;
        br = rsqrtf(tq * (1.0f / Hh) - mean * mean + EPSf);
    }
    __syncthreads();
    const float mean = bm, rstd = br;
    float4 g4 = *reinterpret_cast<const float4*>(&gam[c]);
    float4 b4 = *reinterpret_cast<const float4*>(&bet[c]);
    uint2 o2;
    o2.x = pkh((v[0]-mean)*rstd*g4.x + b4.x, (v[1]-mean)*rstd*g4.y + b4.y);
    o2.y = pkh((v[2]-mean)*rstd*g4.z + b4.z, (v[3]-mean)*rstd*g4.w + b4.w);
    *reinterpret_cast<uint2*>(&oh[base + c]) = o2;
}

// ---------------------------------------------------------------------------
// Flash attention — occ 2, Q hoisted to registers, fixed-max softmax,
// 3-stage KV ring, 1 sync/tile, fp16 ctx output.
// ---------------------------------------------------------------------------
#define FRB 144
#define SQ0 0
#define SKV0 18432
#define KVSTG 18432
#define SMB (SKV0 + 3*KVSTG)
#define FL_SMEM (SMB + 2048)

__device__ __forceinline__ void flash_issue_kv(
    uint32_t base, const __half* K1, const __half* V1,
    int b, int hh, int kt, int tid) {
    int r = tid >> 2, cpart = tid & 3;
    size_t g = ((size_t)(b * Ss + kt * 64 + r)) * Hh + hh * DHh + cpart * 16;
    uint32_t so = (uint32_t)r * FRB + cpart * 32;
    cp16(base + so,         K1 + g); cp16(base + so + 16,        K1 + g + 8);
    cp16(base + 9216 + so,  V1 + g); cp16(base + 9216 + so + 16, V1 + g + 8);
}

__global__ void __launch_bounds__(256, 2) k_flash(
    const __half* __restrict__ Q1,
    const __half* __restrict__ K1,
    const __half* __restrict__ V1,
    const int* __restrict__ mask, __half* __restrict__ CTX) {
    extern __shared__ char smem[];
    const int bh = blockIdx.y;
    const int b = bh / NHh, hh = bh - b * NHh;
    const int q0 = blockIdx.x * 128;
    const uint32_t sb = smem_u32(smem);
    const int tid = threadIdx.x, wid = tid >> 5, lane = tid & 31;
    const float scale = 0.125f;

    {
        int r = tid >> 1, cpart = tid & 1;
        size_t g = ((size_t)(b * Ss + q0 + r)) * Hh + hh * DHh + cpart * 32;
        uint32_t so = (uint32_t)r * FRB + cpart * 64;
#pragma unroll
        for (int i = 0; i < 4; i++)
            cp16(sb + SQ0 + so + 16 * i, Q1 + g + 8 * i);
    }
    flash_issue_kv(sb + SKV0, K1, V1, b, hh, 0, tid);
    cp_commit();
    flash_issue_kv(sb + SKV0 + KVSTG, K1, V1, b, hh, 1, tid);
    cp_commit();

#pragma unroll
    for (int i = 0; i < 4; i++) {
        int kx = tid + i * 256;
        float mb = (mask[b * Ss + kx] == 0) ? -10000.0f : 0.0f;
        *reinterpret_cast<__half*>(smem + SMB + kx * 2) = __float2half_rn(mb);
    }

    float O[8][4];
#pragma unroll
    for (int i = 0; i < 8; i++)
#pragma unroll
        for (int j = 0; j < 4; j++) O[i][j] = 0.f;
    float l0 = 0.f, l1 = 0.f;

    const uint32_t aoff = (uint32_t)(16 * wid + (lane & 15)) * FRB +
                          ((lane >> 4) & 1) * 16;
    const uint32_t koff = (uint32_t)(((lane >> 4) << 3) + (lane & 7)) * FRB +
                          ((lane >> 3) & 1) * 16;
    const uint32_t voff = (uint32_t)(lane & 15) * FRB + ((lane >> 4) & 1) * 16;

    uint32_t qf[4][4];
    cp_wait1();
    __syncthreads();
#pragma unroll
    for (int s = 0; s < 4; s++)
        LDMX4(qf[s], sb + SQ0 + aoff + s * 32);

    for (int kt = 0; kt < 16; kt++) {
        const uint32_t kv = sb + SKV0 + (uint32_t)(kt % 3) * KVSTG;
        if (kt) {
            cp_wait1();
            __syncthreads();
        }
        if (kt + 2 < 16) {
            flash_issue_kv(sb + SKV0 + (uint32_t)((kt + 2) % 3) * KVSTG,
                           K1, V1, b, hh, kt + 2, tid);
            cp_commit();
        }

        uint32_t sh16[8][2];
#pragma unroll
        for (int i = 0; i < 8; i++) { sh16[i][0] = 0u; sh16[i][1] = 0u; }

#pragma unroll
        for (int s = 0; s < 4; s++) {
#pragma unroll
            for (int jp = 0; jp < 4; jp++) {
                uint32_t ka = kv + (uint32_t)(16 * jp) * FRB + koff + s * 32;
                uint32_t kh4[4];
                LDMX4(kh4, ka);
#pragma unroll
                for (int half = 0; half < 2; half++)
                    mmah16(sh16[2 * jp + half], qf[s],
                           kh4[half * 2], kh4[half * 2 + 1]);
            }
        }

        float sacc[8][4];
#pragma unroll
        for (int j = 0; j < 8; j++) {
            float2 s01 = __half22float2(
                *reinterpret_cast<const __half2*>(&sh16[j][0]));
            float2 s23 = __half22float2(
                *reinterpret_cast<const __half2*>(&sh16[j][1]));
            float2 mbv = __half22float2(*reinterpret_cast<const __half2*>(
                smem + SMB + (kt * 64 + 8 * j + 2 * (lane & 3)) * 2));
            float p0 = __expf(s01.x * scale + mbv.x);
            float p1 = __expf(s01.y * scale + mbv.y);
            float p2 = __expf(s23.x * scale + mbv.x);
            float p3 = __expf(s23.y * scale + mbv.y);
            sacc[j][0] = p0; sacc[j][1] = p1; sacc[j][2] = p2; sacc[j][3] = p3;
            l0 += p0 + p1; l1 += p2 + p3;
        }

#pragma unroll
        for (int s = 0; s < 4; s++) {
            uint32_t ph[4];
            ph[0] = pkh(sacc[2 * s][0],     sacc[2 * s][1]);
            ph[1] = pkh(sacc[2 * s][2],     sacc[2 * s][3]);
            ph[2] = pkh(sacc[2 * s + 1][0], sacc[2 * s + 1][1]);
            ph[3] = pkh(sacc[2 * s + 1][2], sacc[2 * s + 1][3]);
#pragma unroll
            for (int dp = 0; dp < 4; dp++) {
                uint32_t va = kv + 9216 + (uint32_t)(16 * s) * FRB + voff + dp * 32;
                uint32_t vh4[4];
                LDMX4T(vh4, va);
#pragma unroll
                for (int half = 0; half < 2; half++)
                    mmah(O[2 * dp + half], ph,
                         vh4[half * 2], vh4[half * 2 + 1]);
            }
        }
    }

    l0 += __shfl_xor_sync(0xffffffffu, l0, 1);
    l0 += __shfl_xor_sync(0xffffffffu, l0, 2);
    l1 += __shfl_xor_sync(0xffffffffu, l1, 1);
    l1 += __shfl_xor_sync(0xffffffffu, l1, 2);
    float i0 = 1.0f / l0, i1 = 1.0f / l1;
    int r0 = b * Ss + q0 + 16 * wid + (lane >> 2);
#pragma unroll
    for (int jd = 0; jd < 8; jd++) {
        int col = hh * DHh + 8 * jd + 2 * (lane & 3);
        *reinterpret_cast<uint32_t*>(&CTX[(size_t)r0 * Hh + col]) =
            pkh(O[jd][0] * i0, O[jd][1] * i0);
        *reinterpret_cast<uint32_t*>(&CTX[(size_t)(r0 + 8) * Hh + col]) =
            pkh(O[jd][2] * i1, O[jd][3] * i1);
    }
}

// ---------------------------------------------------------------------------
// Launch
// ---------------------------------------------------------------------------
extern "C" void kernel_launch(void* const* d_in, const int* in_sizes, int n_in,
                              void* d_out, int out_size) {
    const float* hid  = (const float*)d_in[0];
    const int*   mask = (const int*)  d_in[1];
    const float* pos  = (const float*)d_in[2];
    const float* Wq   = (const float*)d_in[3];
    const float* bq   = (const float*)d_in[4];
    const float* Wk   = (const float*)d_in[5];
    const float* bk   = (const float*)d_in[6];
    const float* Wv   = (const float*)d_in[7];
    const float* bv   = (const float*)d_in[8];
    const float* l1s  = (const float*)d_in[9];
    const float* l1b  = (const float*)d_in[10];
    const float* l2s  = (const float*)d_in[11];
    const float* l2b  = (const float*)d_in[12];
    const float* W1   = (const float*)d_in[13];
    const float* b1   = (const float*)d_in[14];
    const float* W2   = (const float*)d_in[15];
    const float* b2   = (const float*)d_in[16];
    const float* lnfs = (const float*)d_in[17];
    const float* lnfb = (const float*)d_in[18];
    float* out = (float*)d_out;

    float* h;
    __half *parth, *ctx;
    cudaGetSymbolAddress((void**)&h, g_h);
    cudaGetSymbolAddress((void**)&parth, g_parth);
    cudaGetSymbolAddress((void**)&ctx, g_ctx);

    __half *x1, *f1, *q1, *k1, *v1;
    cudaGetSymbolAddress((void**)&x1, g_x1);
    cudaGetSymbolAddress((void**)&f1, g_f1);
    cudaGetSymbolAddress((void**)&q1, g_q1);
    cudaGetSymbolAddress((void**)&k1, g_k1);
    cudaGetSymbolAddress((void**)&v1, g_v1);

    __half *wq, *wk, *wv, *w1, *w2;
    cudaGetSymbolAddress((void**)&wq, g_wqt);
    cudaGetSymbolAddress((void**)&wk, g_wkt);
    cudaGetSymbolAddress((void**)&wv, g_wvt);
    cudaGetSymbolAddress((void**)&w1, g_w1t);
    cudaGetSymbolAddress((void**)&w2, g_w2t);

    cudaFuncSetAttribute(k_mgemm<1>, cudaFuncAttributeMaxDynamicSharedMemorySize, MG_SMEM);
    cudaFuncSetAttribute(k_mgemm<4>, cudaFuncAttributeMaxDynamicSharedMemorySize, MG_SMEM);
    cudaFuncSetAttribute(k_mgemm16, cudaFuncAttributeMaxDynamicSharedMemorySize, MG_SMEM);
    cudaFuncSetAttribute(k_flash,    cudaFuncAttributeMaxDynamicSharedMemorySize, FL_SMEM);

    // weight transpose to fp16 (64x64 tiles)
    k_wt<<<dim3(Hh / 64, Hh / 64, Ll), 256>>>(Wq, wq, Hh, Hh);
    k_wt<<<dim3(Hh / 64, Hh / 64, Ll), 256>>>(Wk, wk, Hh, Hh);
    k_wt<<<dim3(Hh / 64, Hh / 64, Ll), 256>>>(Wv, wv, Hh, Hh);
    k_wt<<<dim3(FFf / 64, Hh / 64, Ll), 256>>>(W1, w1, Hh, FFf);
    k_wt<<<dim3(Hh / 64, FFf / 64, Ll), 256>>>(W2, w2, FFf, Hh);

    // fused: h = hidden + pos, LN1(layer 0) -> x1
    k_addposln<<<Mm, 192>>>(hid, pos, h, l1s, l1b, x1);

    for (int l = 0; l < Ll; l++) {
        const size_t wOff = (size_t)l * Hh * Hh;
        const size_t fOff = (size_t)l * Hh * FFf;

        // fused QKV (fp16 accum) -> fp16
        {
            GPtrs P = {};
            P.w[0] = wq + wOff; P.w[1] = wk + wOff; P.w[2] = wv + wOff;
            P.bias[0] = bq + l * Hh; P.bias[1] = bk + l * Hh; P.bias[2] = bv + l * Hh;
            P.outh[0] = q1; P.outh[1] = k1; P.outh[2] = v1;
            k_mgemm16<<<dim3(Hh / 128, Mm / 128, 3), 256, MG_SMEM>>>(
                x1, P, Hh, Hh, Hh);
        }

        // flash -> fp16 ctx
        k_flash<<<dim3(Ss / 128, Bb * NHh), 256, FL_SMEM>>>(
            q1, k1, v1, mask, ctx);

        // h += ctx; LN2 -> x1
        k_lnadd<<<Mm, 192>>>(ctx, h, l2s + l * Hh, l2b + l * Hh, x1);

        // FFN1: GELU(x @ W1 + b1) -> fp16
        {
            GPtrs P = {};
            P.w[0] = w1 + fOff;
            P.bias[0] = b1 + l * FFf;
            P.outh[0] = f1;
            k_mgemm<1><<<dim3(FFf / 128, Mm / 128, 1), 256, MG_SMEM>>>(
                x1, P, Hh, Hh, FFf);
        }
        // FFN2 split-K x3 partials (fp16)
        {
            GPtrs P = {};
            P.w[0] = w2 + fOff;        P.w[1] = w2 + fOff + 1024;
            P.w[2] = w2 + fOff + 2048;
            P.aoff[0] = 0; P.aoff[1] = 1024; P.aoff[2] = 2048;
            P.outh[0] = parth;
            P.outh[1] = parth + (size_t)Mm * Hh;
            P.outh[2] = parth + 2 * (size_t)Mm * Hh;
            k_mgemm<4><<<dim3(Hh / 128, Mm / 128, 3), 256, MG_SMEM>>>(
                f1, P, 1024, FFf, Hh);
        }
        // reduce + residual, fused with next LN1 (or final LN on last layer)
        if (l + 1 < Ll) {
            k_redln<<<Mm, 192>>>(
                parth, parth + (size_t)Mm * Hh, parth + 2 * (size_t)Mm * Hh,
                b2 + l * Hh, h, l1s + (l + 1) * Hh, l1b + (l + 1) * Hh, x1);
        } else {
            k_redlnf<<<Mm, 192>>>(
                parth, parth + (size_t)Mm * Hh, parth + 2 * (size_t)Mm * Hh,
                b2 + l * Hh, h, lnfs, lnfb, out);
        }
    }
}